// round 1
// baseline (speedup 1.0000x reference)
#include <cuda_runtime.h>
#include <cstdint>
#include <cstddef>

#define T_STEPS 512
#define BATCH   64
#define INDIM   512
#define HID     512
#define G4      2048   // 4*HID

// 256 MB scratch for precomputed x@W + b  ([T*B, 4H])
__device__ float g_xw[(size_t)T_STEPS * BATCH * G4];
__device__ unsigned g_bar;

__global__ void reset_kernel() { g_bar = 0u; }

// ---------------------------------------------------------------------------
// SGEMM: g_xw[M,N] = A[M,K] @ Bw[K,N] + bias[N]
// M = T*B = 32768, N = 2048, K = 512. 128x128 tile, BK=16, 8x8 per thread.
// ---------------------------------------------------------------------------
#define BM 128
#define BN 128
#define BK 16

__global__ __launch_bounds__(256) void sgemm_bias_kernel(
    const float* __restrict__ A, const float* __restrict__ Bw,
    const float* __restrict__ bias) {
  const int M = T_STEPS * BATCH;
  const int N = G4;
  const int K = INDIM;
  (void)M;

  __shared__ float As[BK][BM + 4];
  __shared__ float Bs[BK][BN];

  const int tid = threadIdx.x;
  const int tx = tid & 15;      // 0..15 (n)
  const int ty = tid >> 4;      // 0..15 (m)
  const int m0 = blockIdx.y * BM;
  const int n0 = blockIdx.x * BN;

  // load index mapping (512 float4 per tile, 2 per thread)
  const int i0 = tid, i1 = tid + 256;
  const int ar0 = i0 >> 2, ac0 = (i0 & 3) * 4;
  const int ar1 = i1 >> 2, ac1 = (i1 & 3) * 4;
  const int br0 = i0 >> 5, bc0 = (i0 & 31) * 4;
  const int br1 = i1 >> 5, bc1 = (i1 & 31) * 4;

  float acc[8][8];
#pragma unroll
  for (int i = 0; i < 8; ++i)
#pragma unroll
    for (int j = 0; j < 8; ++j) acc[i][j] = 0.0f;

  // prefetch k-tile 0
  float4 pa0 = *(const float4*)(A + (size_t)(m0 + ar0) * K + ac0);
  float4 pa1 = *(const float4*)(A + (size_t)(m0 + ar1) * K + ac1);
  float4 pb0 = *(const float4*)(Bw + (size_t)br0 * N + n0 + bc0);
  float4 pb1 = *(const float4*)(Bw + (size_t)br1 * N + n0 + bc1);

  const int NKT = K / BK;  // 32
  for (int kt = 0; kt < NKT; ++kt) {
    // commit prefetched tile to smem (A transposed)
    As[ac0 + 0][ar0] = pa0.x; As[ac0 + 1][ar0] = pa0.y;
    As[ac0 + 2][ar0] = pa0.z; As[ac0 + 3][ar0] = pa0.w;
    As[ac1 + 0][ar1] = pa1.x; As[ac1 + 1][ar1] = pa1.y;
    As[ac1 + 2][ar1] = pa1.z; As[ac1 + 3][ar1] = pa1.w;
    *(float4*)&Bs[br0][bc0] = pb0;
    *(float4*)&Bs[br1][bc1] = pb1;
    __syncthreads();

    if (kt + 1 < NKT) {
      const int ko = (kt + 1) * BK;
      pa0 = *(const float4*)(A + (size_t)(m0 + ar0) * K + ko + ac0);
      pa1 = *(const float4*)(A + (size_t)(m0 + ar1) * K + ko + ac1);
      pb0 = *(const float4*)(Bw + (size_t)(ko + br0) * N + n0 + bc0);
      pb1 = *(const float4*)(Bw + (size_t)(ko + br1) * N + n0 + bc1);
    }

#pragma unroll
    for (int k = 0; k < BK; ++k) {
      float4 ra0 = *(const float4*)&As[k][ty * 4];
      float4 ra1 = *(const float4*)&As[k][64 + ty * 4];
      float4 rb0 = *(const float4*)&Bs[k][tx * 4];
      float4 rb1 = *(const float4*)&Bs[k][64 + tx * 4];
      float rm[8] = {ra0.x, ra0.y, ra0.z, ra0.w, ra1.x, ra1.y, ra1.z, ra1.w};
      float rn[8] = {rb0.x, rb0.y, rb0.z, rb0.w, rb1.x, rb1.y, rb1.z, rb1.w};
#pragma unroll
      for (int i = 0; i < 8; ++i)
#pragma unroll
        for (int j = 0; j < 8; ++j) acc[i][j] = fmaf(rm[i], rn[j], acc[i][j]);
    }
    __syncthreads();
  }

  float4 blo = *(const float4*)(bias + n0 + tx * 4);
  float4 bhi = *(const float4*)(bias + n0 + 64 + tx * 4);
#pragma unroll
  for (int i = 0; i < 8; ++i) {
    const int m = m0 + ((i < 4) ? (ty * 4 + i) : (64 + ty * 4 + (i - 4)));
    float* cp = g_xw + (size_t)m * N + n0;
    float4 v0 = make_float4(acc[i][0] + blo.x, acc[i][1] + blo.y,
                            acc[i][2] + blo.z, acc[i][3] + blo.w);
    float4 v1 = make_float4(acc[i][4] + bhi.x, acc[i][5] + bhi.y,
                            acc[i][6] + bhi.z, acc[i][7] + bhi.w);
    *(float4*)(cp + tx * 4) = v0;
    *(float4*)(cp + 64 + tx * 4) = v1;
  }
}

// ---------------------------------------------------------------------------
// Persistent recurrence kernel. 128 CTAs x 128 threads, grid barrier per step.
// CTA c owns h-columns [4c, 4c+4). U slice (16 cols x 512) lives in smem for
// the whole kernel; a_{t-1} is staged into padded smem each step.
// ---------------------------------------------------------------------------
#define RGRID    128
#define RTHREADS 128
#define AS_STRIDE 516   // 512 + 4 floats pad (16B) -> conflict-free float4 rows

__device__ __forceinline__ float sigmoidf_(float x) {
  return 1.0f / (1.0f + __expf(-x));
}

__global__ __launch_bounds__(RTHREADS) void recur_kernel(
    const float* __restrict__ a0, const float* __restrict__ U,
    float* __restrict__ out) {
  extern __shared__ float sm[];
  float* Us = sm;                 // 16 * 512
  float* As = sm + 16 * 512;      // 64 * AS_STRIDE

  const int tid = threadIdx.x;
  const int hb = blockIdx.x * 4;

  // preload U slice: local col j = i*4 + gate  <->  global col gate*H + hb + i
  for (int idx = tid; idx < 512 * 4; idx += RTHREADS) {
    const int k = idx >> 2, gate = idx & 3;
    float4 v = *(const float4*)(U + (size_t)k * G4 + gate * HID + hb);
    Us[(0 * 4 + gate) * 512 + k] = v.x;
    Us[(1 * 4 + gate) * 512 + k] = v.y;
    Us[(2 * 4 + gate) * 512 + k] = v.z;
    Us[(3 * 4 + gate) * 512 + k] = v.w;
  }

  const int bg = tid & 31;        // batch group: b in {bg, bg+32}
  const int cg = tid >> 5;        // h offset i = cg (0..3)
  const int h = hb + cg;
  const float* U0 = Us + (cg * 4 + 0) * 512;
  const float* U1 = Us + (cg * 4 + 1) * 512;
  const float* U2 = Us + (cg * 4 + 2) * 512;
  const float* U3 = Us + (cg * 4 + 3) * 512;

  unsigned target = 0;

  for (int t = 0; t < T_STEPS; ++t) {
    // ---- stage a_{t-1} into smem (L2-coherent loads; writers are other SMs)
    const float* ap = (t == 0) ? a0 : (out + (size_t)(t - 1) * BATCH * HID);
    for (int idx = tid; idx < BATCH * (HID / 4); idx += RTHREADS) {
      const int b = idx >> 7, k4 = idx & 127;
      float4 v = __ldcg((const float4*)(ap + b * HID + k4 * 4));
      *(float4*)(As + b * AS_STRIDE + k4 * 4) = v;
    }
    // ---- accumulators init = xw projection (g = xw + a@U)
    const float* xwp = g_xw + (size_t)t * BATCH * G4;
    float acc[2][4];
#pragma unroll
    for (int g = 0; g < 4; ++g) {
      acc[0][g] = __ldg(xwp + (size_t)bg * G4 + g * HID + h);
      acc[1][g] = __ldg(xwp + (size_t)(bg + 32) * G4 + g * HID + h);
    }
    __syncthreads();

    // ---- dot products: [2 b] x [4 gates] over K=512
    const float* A0p = As + bg * AS_STRIDE;
    const float* A1p = As + (bg + 32) * AS_STRIDE;
#pragma unroll 4
    for (int k4 = 0; k4 < 128; ++k4) {
      float4 av0 = *(const float4*)(A0p + k4 * 4);
      float4 av1 = *(const float4*)(A1p + k4 * 4);
      float4 u0 = *(const float4*)(U0 + k4 * 4);
      float4 u1 = *(const float4*)(U1 + k4 * 4);
      float4 u2 = *(const float4*)(U2 + k4 * 4);
      float4 u3 = *(const float4*)(U3 + k4 * 4);
      acc[0][0] = fmaf(av0.x, u0.x, fmaf(av0.y, u0.y, fmaf(av0.z, u0.z, fmaf(av0.w, u0.w, acc[0][0]))));
      acc[0][1] = fmaf(av0.x, u1.x, fmaf(av0.y, u1.y, fmaf(av0.z, u1.z, fmaf(av0.w, u1.w, acc[0][1]))));
      acc[0][2] = fmaf(av0.x, u2.x, fmaf(av0.y, u2.y, fmaf(av0.z, u2.z, fmaf(av0.w, u2.w, acc[0][2]))));
      acc[0][3] = fmaf(av0.x, u3.x, fmaf(av0.y, u3.y, fmaf(av0.z, u3.z, fmaf(av0.w, u3.w, acc[0][3]))));
      acc[1][0] = fmaf(av1.x, u0.x, fmaf(av1.y, u0.y, fmaf(av1.z, u0.z, fmaf(av1.w, u0.w, acc[1][0]))));
      acc[1][1] = fmaf(av1.x, u1.x, fmaf(av1.y, u1.y, fmaf(av1.z, u1.z, fmaf(av1.w, u1.w, acc[1][1]))));
      acc[1][2] = fmaf(av1.x, u2.x, fmaf(av1.y, u2.y, fmaf(av1.z, u2.z, fmaf(av1.w, u2.w, acc[1][2]))));
      acc[1][3] = fmaf(av1.x, u3.x, fmaf(av1.y, u3.y, fmaf(av1.z, u3.z, fmaf(av1.w, u3.w, acc[1][3]))));
    }

    // ---- gates + state update + output
#pragma unroll
    for (int r = 0; r < 2; ++r) {
      const int b = bg + r * 32;
      const float gu = sigmoidf_(acc[r][0]);
      const float gf = sigmoidf_(acc[r][1]);
      const float go = sigmoidf_(acc[r][2]);
      const float cd = tanhf(acc[r][3]);
      const float apv = As[b * AS_STRIDE + h];       // a_{t-1}[b][h]
      const float ct = gu * cd + gf * apv;
      out[(size_t)t * BATCH * HID + b * HID + h] = go * tanhf(ct);
    }

    // ---- grid barrier (release: fence all threads, then sync, then arrive)
    target += RGRID;
    __threadfence();
    __syncthreads();
    if (tid == 0) {
      atomicAdd(&g_bar, 1u);
      while (*(volatile unsigned*)&g_bar < target) { __nanosleep(64); }
      __threadfence();
    }
    __syncthreads();
  }
}

// ---------------------------------------------------------------------------
extern "C" void kernel_launch(void* const* d_in, const int* in_sizes, int n_in,
                              void* d_out, int out_size) {
  (void)in_sizes; (void)n_in; (void)out_size;
  const float* x    = (const float*)d_in[0];  // [T, B, I]
  const float* a0   = (const float*)d_in[1];  // [B, H]
  const float* W    = (const float*)d_in[2];  // [I, 4H]
  const float* U    = (const float*)d_in[3];  // [H, 4H]
  const float* bias = (const float*)d_in[4];  // [4H]
  float* out = (float*)d_out;                 // [T, B, H]

  const size_t smem = (size_t)(16 * 512 + 64 * AS_STRIDE) * sizeof(float);
  cudaFuncSetAttribute(recur_kernel, cudaFuncAttributeMaxDynamicSharedMemorySize,
                       (int)smem);

  reset_kernel<<<1, 1>>>();
  dim3 grid(G4 / BN, (T_STEPS * BATCH) / BM);  // (16, 256)
  sgemm_bias_kernel<<<grid, 256>>>(x, W, bias);
  recur_kernel<<<RGRID, RTHREADS, smem>>>(a0, U, out);
}

// round 3
// speedup vs baseline: 1.0581x; 1.0581x over previous
#include <cuda_runtime.h>
#include <cstdint>
#include <cstddef>

#define T_STEPS 512
#define BATCH   64
#define INDIM   512
#define HID     512
#define G4      2048   // 4*HID

// scratch: precomputed x@W + b  ([T*B, 4H]) and transposed (tf32-rounded) W
__device__ float g_xw[(size_t)T_STEPS * BATCH * G4];
__device__ float g_Wt[(size_t)G4 * INDIM];
__device__ unsigned g_bar;

__device__ __forceinline__ uint32_t f2tf32(float f) {
  uint32_t r;
  asm("cvt.rna.tf32.f32 %0, %1;" : "=r"(r) : "f"(f));
  return r;
}

__device__ __forceinline__ void mma_tf32(float* d, const uint32_t* a,
                                         const uint32_t* b) {
  asm volatile(
      "mma.sync.aligned.m16n8k8.row.col.f32.tf32.tf32.f32 "
      "{%0,%1,%2,%3}, {%4,%5,%6,%7}, {%8,%9}, {%0,%1,%2,%3};"
      : "+f"(d[0]), "+f"(d[1]), "+f"(d[2]), "+f"(d[3])
      : "r"(a[0]), "r"(a[1]), "r"(a[2]), "r"(a[3]), "r"(b[0]), "r"(b[1]));
}

// ---------------------------------------------------------------------------
// W transpose + tf32 rounding: g_Wt[n][k] = tf32(W[k][n]). Resets grid barrier.
// ---------------------------------------------------------------------------
__global__ __launch_bounds__(256) void transpose_kernel(const float* __restrict__ W) {
  __shared__ float tile[32][33];
  const int n0 = blockIdx.x * 32, k0 = blockIdx.y * 32;
  const int tx = threadIdx.x, ty = threadIdx.y;  // 32 x 8
#pragma unroll
  for (int i = 0; i < 32; i += 8)
    tile[ty + i][tx] = W[(size_t)(k0 + ty + i) * G4 + n0 + tx];
  __syncthreads();
#pragma unroll
  for (int i = 0; i < 32; i += 8)
    g_Wt[(size_t)(n0 + ty + i) * INDIM + k0 + tx] =
        __uint_as_float(f2tf32(tile[tx][ty + i]));
  if (blockIdx.x == 0 && blockIdx.y == 0 && tx == 0 && ty == 0) g_bar = 0u;
}

// ---------------------------------------------------------------------------
// TF32 tensor-core GEMM (mma.sync): g_xw[M,N] = A[M,K] @ Wt^T + bias
// M=32768, N=2048, K=512. CTA tile 128x128, BK=32, 8 warps (2x4), 64x32/warp.
// ---------------------------------------------------------------------------
#define BM 128
#define BN 128
#define BK 32
#define SSTR 36   // smem row stride (32 + 4 pad floats)

__global__ __launch_bounds__(256) void xw_tc_kernel(const float* __restrict__ A,
                                                    const float* __restrict__ bias) {
  extern __shared__ float smem[];
  // As[2][128][SSTR], Bs[2][128][SSTR]
  float* As[2] = {smem, smem + BM * SSTR};
  float* Bs[2] = {smem + 2 * BM * SSTR, smem + 3 * BM * SSTR};

  const int tid = threadIdx.x;
  const int lane = tid & 31, wid = tid >> 5;
  const int wm = (wid >> 2) * 64;   // warp m offset in tile
  const int wn = (wid & 3) * 32;    // warp n offset in tile
  const int g = lane >> 2, tg = lane & 3;
  const int n0 = blockIdx.x * BN;   // 16 n-tiles (fast dim -> A L2 reuse)
  const int m0 = blockIdx.y * BM;   // 256 m-tiles

  // stage-load mapping: 1024 float4 per tile, 4 per thread
  const int lr = tid >> 3;          // row 0..127 (every 2 tids share? no: tid>>3 over j)
  const int lc = (tid & 7) * 4;     // k-col (float4)

  float acc[4][4][4];
#pragma unroll
  for (int i = 0; i < 4; ++i)
#pragma unroll
    for (int j = 0; j < 4; ++j)
#pragma unroll
      for (int q = 0; q < 4; ++q) acc[i][j][q] = 0.0f;

  // prefetch k-tile 0  (4 float4 of A, 4 of B per thread)
  float4 pa[4], pb[4];
#pragma unroll
  for (int j = 0; j < 4; ++j) {
    const int r = lr + j * 32;
    pa[j] = *(const float4*)(A + (size_t)(m0 + r) * INDIM + lc);
    pb[j] = *(const float4*)(g_Wt + (size_t)(n0 + r) * INDIM + lc);
  }

  const int NKT = INDIM / BK;  // 16
  for (int kt = 0; kt < NKT; ++kt) {
    const int s = kt & 1;
    // commit prefetched tiles (A converted to tf32; B pre-rounded)
#pragma unroll
    for (int j = 0; j < 4; ++j) {
      const int r = lr + j * 32;
      float* ap = As[s] + r * SSTR + lc;
      ap[0] = __uint_as_float(f2tf32(pa[j].x));
      ap[1] = __uint_as_float(f2tf32(pa[j].y));
      ap[2] = __uint_as_float(f2tf32(pa[j].z));
      ap[3] = __uint_as_float(f2tf32(pa[j].w));
      *(float4*)(Bs[s] + r * SSTR + lc) = pb[j];
    }
    __syncthreads();

    if (kt + 1 < NKT) {
      const int ko = (kt + 1) * BK;
#pragma unroll
      for (int j = 0; j < 4; ++j) {
        const int r = lr + j * 32;
        pa[j] = *(const float4*)(A + (size_t)(m0 + r) * INDIM + ko + lc);
        pb[j] = *(const float4*)(g_Wt + (size_t)(n0 + r) * INDIM + ko + lc);
      }
    }

    // compute: 4 k8-steps, 16 mma each
#pragma unroll
    for (int k8 = 0; k8 < 4; ++k8) {
      const int kb = k8 * 8;
      uint32_t afr[4][4], bfr[4][2];
#pragma unroll
      for (int mf = 0; mf < 4; ++mf) {
        const float* ap = As[s] + (wm + mf * 16) * SSTR + kb;
        afr[mf][0] = __float_as_uint(ap[g * SSTR + tg]);
        afr[mf][1] = __float_as_uint(ap[(g + 8) * SSTR + tg]);
        afr[mf][2] = __float_as_uint(ap[g * SSTR + tg + 4]);
        afr[mf][3] = __float_as_uint(ap[(g + 8) * SSTR + tg + 4]);
      }
#pragma unroll
      for (int nf = 0; nf < 4; ++nf) {
        const float* bp = Bs[s] + (wn + nf * 8) * SSTR + kb;
        bfr[nf][0] = __float_as_uint(bp[g * SSTR + tg]);
        bfr[nf][1] = __float_as_uint(bp[g * SSTR + tg + 4]);
      }
#pragma unroll
      for (int mf = 0; mf < 4; ++mf)
#pragma unroll
        for (int nf = 0; nf < 4; ++nf)
          mma_tf32(acc[mf][nf], afr[mf], bfr[nf]);
    }
    __syncthreads();
  }

  // epilogue: D fragment layout: c0 (g, 2tg) c1 (g, 2tg+1) c2 (g+8, ...) c3
  float2 bv[4];
#pragma unroll
  for (int nf = 0; nf < 4; ++nf)
    bv[nf] = *(const float2*)(bias + n0 + wn + nf * 8 + tg * 2);
#pragma unroll
  for (int mf = 0; mf < 4; ++mf) {
    const int row0 = m0 + wm + mf * 16 + g;
#pragma unroll
    for (int nf = 0; nf < 4; ++nf) {
      const int col = n0 + wn + nf * 8 + tg * 2;
      float2 v0 = make_float2(acc[mf][nf][0] + bv[nf].x, acc[mf][nf][1] + bv[nf].y);
      float2 v1 = make_float2(acc[mf][nf][2] + bv[nf].x, acc[mf][nf][3] + bv[nf].y);
      *(float2*)(g_xw + (size_t)row0 * G4 + col) = v0;
      *(float2*)(g_xw + (size_t)(row0 + 8) * G4 + col) = v1;
    }
  }
}

// ---------------------------------------------------------------------------
// Persistent recurrence kernel (unchanged, known-good). 128 CTAs x 128 thr.
// ---------------------------------------------------------------------------
#define RGRID    128
#define RTHREADS 128
#define AS_STRIDE 516

__device__ __forceinline__ float sigmoidf_(float x) {
  return 1.0f / (1.0f + __expf(-x));
}

__global__ __launch_bounds__(RTHREADS) void recur_kernel(
    const float* __restrict__ a0, const float* __restrict__ U,
    float* __restrict__ out) {
  extern __shared__ float sm[];
  float* Us = sm;                 // 16 * 512
  float* As = sm + 16 * 512;      // 64 * AS_STRIDE

  const int tid = threadIdx.x;
  const int hb = blockIdx.x * 4;

  for (int idx = tid; idx < 512 * 4; idx += RTHREADS) {
    const int k = idx >> 2, gate = idx & 3;
    float4 v = *(const float4*)(U + (size_t)k * G4 + gate * HID + hb);
    Us[(0 * 4 + gate) * 512 + k] = v.x;
    Us[(1 * 4 + gate) * 512 + k] = v.y;
    Us[(2 * 4 + gate) * 512 + k] = v.z;
    Us[(3 * 4 + gate) * 512 + k] = v.w;
  }

  const int bg = tid & 31;
  const int cg = tid >> 5;
  const int h = hb + cg;
  const float* U0 = Us + (cg * 4 + 0) * 512;
  const float* U1 = Us + (cg * 4 + 1) * 512;
  const float* U2 = Us + (cg * 4 + 2) * 512;
  const float* U3 = Us + (cg * 4 + 3) * 512;

  unsigned target = 0;

  for (int t = 0; t < T_STEPS; ++t) {
    const float* ap = (t == 0) ? a0 : (out + (size_t)(t - 1) * BATCH * HID);
    for (int idx = tid; idx < BATCH * (HID / 4); idx += RTHREADS) {
      const int b = idx >> 7, k4 = idx & 127;
      float4 v = __ldcg((const float4*)(ap + b * HID + k4 * 4));
      *(float4*)(As + b * AS_STRIDE + k4 * 4) = v;
    }
    const float* xwp = g_xw + (size_t)t * BATCH * G4;
    float acc[2][4];
#pragma unroll
    for (int g = 0; g < 4; ++g) {
      acc[0][g] = __ldg(xwp + (size_t)bg * G4 + g * HID + h);
      acc[1][g] = __ldg(xwp + (size_t)(bg + 32) * G4 + g * HID + h);
    }
    __syncthreads();

    const float* A0p = As + bg * AS_STRIDE;
    const float* A1p = As + (bg + 32) * AS_STRIDE;
#pragma unroll 4
    for (int k4 = 0; k4 < 128; ++k4) {
      float4 av0 = *(const float4*)(A0p + k4 * 4);
      float4 av1 = *(const float4*)(A1p + k4 * 4);
      float4 u0 = *(const float4*)(U0 + k4 * 4);
      float4 u1 = *(const float4*)(U1 + k4 * 4);
      float4 u2 = *(const float4*)(U2 + k4 * 4);
      float4 u3 = *(const float4*)(U3 + k4 * 4);
      acc[0][0] = fmaf(av0.x, u0.x, fmaf(av0.y, u0.y, fmaf(av0.z, u0.z, fmaf(av0.w, u0.w, acc[0][0]))));
      acc[0][1] = fmaf(av0.x, u1.x, fmaf(av0.y, u1.y, fmaf(av0.z, u1.z, fmaf(av0.w, u1.w, acc[0][1]))));
      acc[0][2] = fmaf(av0.x, u2.x, fmaf(av0.y, u2.y, fmaf(av0.z, u2.z, fmaf(av0.w, u2.w, acc[0][2]))));
      acc[0][3] = fmaf(av0.x, u3.x, fmaf(av0.y, u3.y, fmaf(av0.z, u3.z, fmaf(av0.w, u3.w, acc[0][3]))));
      acc[1][0] = fmaf(av1.x, u0.x, fmaf(av1.y, u0.y, fmaf(av1.z, u0.z, fmaf(av1.w, u0.w, acc[1][0]))));
      acc[1][1] = fmaf(av1.x, u1.x, fmaf(av1.y, u1.y, fmaf(av1.z, u1.z, fmaf(av1.w, u1.w, acc[1][1]))));
      acc[1][2] = fmaf(av1.x, u2.x, fmaf(av1.y, u2.y, fmaf(av1.z, u2.z, fmaf(av1.w, u2.w, acc[1][2]))));
      acc[1][3] = fmaf(av1.x, u3.x, fmaf(av1.y, u3.y, fmaf(av1.z, u3.z, fmaf(av1.w, u3.w, acc[1][3]))));
    }

#pragma unroll
    for (int r = 0; r < 2; ++r) {
      const int b = bg + r * 32;
      const float gu = sigmoidf_(acc[r][0]);
      const float gf = sigmoidf_(acc[r][1]);
      const float go = sigmoidf_(acc[r][2]);
      const float cd = tanhf(acc[r][3]);
      const float apv = As[b * AS_STRIDE + h];
      const float ct = gu * cd + gf * apv;
      out[(size_t)t * BATCH * HID + b * HID + h] = go * tanhf(ct);
    }

    target += RGRID;
    __threadfence();
    __syncthreads();
    if (tid == 0) {
      atomicAdd(&g_bar, 1u);
      while (*(volatile unsigned*)&g_bar < target) { __nanosleep(64); }
      __threadfence();
    }
    __syncthreads();
  }
}

// ---------------------------------------------------------------------------
extern "C" void kernel_launch(void* const* d_in, const int* in_sizes, int n_in,
                              void* d_out, int out_size) {
  (void)in_sizes; (void)n_in; (void)out_size;
  const float* x    = (const float*)d_in[0];  // [T, B, I]
  const float* a0   = (const float*)d_in[1];  // [B, H]
  const float* W    = (const float*)d_in[2];  // [I, 4H]
  const float* U    = (const float*)d_in[3];  // [H, 4H]
  const float* bias = (const float*)d_in[4];  // [4H]
  float* out = (float*)d_out;                 // [T, B, H]

  const int smemG = 4 * BM * SSTR * sizeof(float);  // 73728 B
  cudaFuncSetAttribute(xw_tc_kernel, cudaFuncAttributeMaxDynamicSharedMemorySize,
                       smemG);
  const size_t smemR = (size_t)(16 * 512 + 64 * AS_STRIDE) * sizeof(float);
  cudaFuncSetAttribute(recur_kernel, cudaFuncAttributeMaxDynamicSharedMemorySize,
                       (int)smemR);

  transpose_kernel<<<dim3(G4 / 32, INDIM / 32), dim3(32, 8)>>>(W);
  xw_tc_kernel<<<dim3(G4 / BN, (T_STEPS * BATCH) / BM), 256, smemG>>>(x, bias);
  recur_kernel<<<RGRID, RTHREADS, smemR>>>(a0, U, out);
}

// round 4
// speedup vs baseline: 1.4127x; 1.3351x over previous
#include <cuda_runtime.h>
#include <cstdint>
#include <cstddef>

#define T_STEPS 512
#define BATCH   64
#define INDIM   512
#define HID     512
#define G4      2048   // 4*HID

// scratch: precomputed x@W+b, transposed tf32 W, ping-pong tf32 hidden state
__device__ float g_xw[(size_t)T_STEPS * BATCH * G4];
__device__ float g_Wt[(size_t)G4 * INDIM];
__device__ float g_atf[2][BATCH * HID];
__device__ unsigned g_bar;

__device__ __forceinline__ uint32_t f2tf32(float f) {
  uint32_t r;
  asm("cvt.rna.tf32.f32 %0, %1;" : "=r"(r) : "f"(f));
  return r;
}
__device__ __forceinline__ float f2tf32f(float f) {
  return __uint_as_float(f2tf32(f));
}

__device__ __forceinline__ void mma_tf32(float* d, const uint32_t* a,
                                         const uint32_t* b) {
  asm volatile(
      "mma.sync.aligned.m16n8k8.row.col.f32.tf32.tf32.f32 "
      "{%0,%1,%2,%3}, {%4,%5,%6,%7}, {%8,%9}, {%0,%1,%2,%3};"
      : "+f"(d[0]), "+f"(d[1]), "+f"(d[2]), "+f"(d[3])
      : "r"(a[0]), "r"(a[1]), "r"(a[2]), "r"(a[3]), "r"(b[0]), "r"(b[1]));
}

// ---------------------------------------------------------------------------
// W transpose + tf32 rounding; also rounds a0 into g_atf[0]; resets barrier.
// ---------------------------------------------------------------------------
__global__ __launch_bounds__(256) void transpose_kernel(const float* __restrict__ W,
                                                        const float* __restrict__ a0) {
  __shared__ float tile[32][33];
  const int n0 = blockIdx.x * 32, k0 = blockIdx.y * 32;
  const int tx = threadIdx.x, ty = threadIdx.y;  // 32 x 8
#pragma unroll
  for (int i = 0; i < 32; i += 8)
    tile[ty + i][tx] = W[(size_t)(k0 + ty + i) * G4 + n0 + tx];
  __syncthreads();
#pragma unroll
  for (int i = 0; i < 32; i += 8)
    g_Wt[(size_t)(n0 + ty + i) * INDIM + k0 + tx] = f2tf32f(tile[tx][ty + i]);
  if (blockIdx.y == 0) {  // 64 blocks x 256 thr: round a0 (32768 elems)
    const int fl = blockIdx.x * 256 + ty * 32 + tx;
    g_atf[0][fl] = f2tf32f(a0[fl]);
    g_atf[0][fl + 16384] = f2tf32f(a0[fl + 16384]);
  }
  if (blockIdx.x == 0 && blockIdx.y == 0 && tx == 0 && ty == 0) g_bar = 0u;
}

// ---------------------------------------------------------------------------
// TF32 tensor-core GEMM (unchanged, known-good): g_xw = x@W + bias
// ---------------------------------------------------------------------------
#define BM 128
#define BN 128
#define BK 32
#define SSTR 36

__global__ __launch_bounds__(256) void xw_tc_kernel(const float* __restrict__ A,
                                                    const float* __restrict__ bias) {
  extern __shared__ float smem[];
  float* As[2] = {smem, smem + BM * SSTR};
  float* Bs[2] = {smem + 2 * BM * SSTR, smem + 3 * BM * SSTR};

  const int tid = threadIdx.x;
  const int lane = tid & 31, wid = tid >> 5;
  const int wm = (wid >> 2) * 64;
  const int wn = (wid & 3) * 32;
  const int g = lane >> 2, tg = lane & 3;
  const int n0 = blockIdx.x * BN;
  const int m0 = blockIdx.y * BM;

  const int lr = tid >> 3;
  const int lc = (tid & 7) * 4;

  float acc[4][4][4];
#pragma unroll
  for (int i = 0; i < 4; ++i)
#pragma unroll
    for (int j = 0; j < 4; ++j)
#pragma unroll
      for (int q = 0; q < 4; ++q) acc[i][j][q] = 0.0f;

  float4 pa[4], pb[4];
#pragma unroll
  for (int j = 0; j < 4; ++j) {
    const int r = lr + j * 32;
    pa[j] = *(const float4*)(A + (size_t)(m0 + r) * INDIM + lc);
    pb[j] = *(const float4*)(g_Wt + (size_t)(n0 + r) * INDIM + lc);
  }

  const int NKT = INDIM / BK;  // 16
  for (int kt = 0; kt < NKT; ++kt) {
    const int s = kt & 1;
#pragma unroll
    for (int j = 0; j < 4; ++j) {
      const int r = lr + j * 32;
      float* ap = As[s] + r * SSTR + lc;
      ap[0] = f2tf32f(pa[j].x);
      ap[1] = f2tf32f(pa[j].y);
      ap[2] = f2tf32f(pa[j].z);
      ap[3] = f2tf32f(pa[j].w);
      *(float4*)(Bs[s] + r * SSTR + lc) = pb[j];
    }
    __syncthreads();

    if (kt + 1 < NKT) {
      const int ko = (kt + 1) * BK;
#pragma unroll
      for (int j = 0; j < 4; ++j) {
        const int r = lr + j * 32;
        pa[j] = *(const float4*)(A + (size_t)(m0 + r) * INDIM + ko + lc);
        pb[j] = *(const float4*)(g_Wt + (size_t)(n0 + r) * INDIM + ko + lc);
      }
    }

#pragma unroll
    for (int k8 = 0; k8 < 4; ++k8) {
      const int kb = k8 * 8;
      uint32_t afr[4][4], bfr[4][2];
#pragma unroll
      for (int mf = 0; mf < 4; ++mf) {
        const float* ap = As[s] + (wm + mf * 16) * SSTR + kb;
        afr[mf][0] = __float_as_uint(ap[g * SSTR + tg]);
        afr[mf][1] = __float_as_uint(ap[(g + 8) * SSTR + tg]);
        afr[mf][2] = __float_as_uint(ap[g * SSTR + tg + 4]);
        afr[mf][3] = __float_as_uint(ap[(g + 8) * SSTR + tg + 4]);
      }
#pragma unroll
      for (int nf = 0; nf < 4; ++nf) {
        const float* bp = Bs[s] + (wn + nf * 8) * SSTR + kb;
        bfr[nf][0] = __float_as_uint(bp[g * SSTR + tg]);
        bfr[nf][1] = __float_as_uint(bp[g * SSTR + tg + 4]);
      }
#pragma unroll
      for (int mf = 0; mf < 4; ++mf)
#pragma unroll
        for (int nf = 0; nf < 4; ++nf)
          mma_tf32(acc[mf][nf], afr[mf], bfr[nf]);
    }
    __syncthreads();
  }

  float2 bv[4];
#pragma unroll
  for (int nf = 0; nf < 4; ++nf)
    bv[nf] = *(const float2*)(bias + n0 + wn + nf * 8 + tg * 2);
#pragma unroll
  for (int mf = 0; mf < 4; ++mf) {
    const int row0 = m0 + wm + mf * 16 + g;
#pragma unroll
    for (int nf = 0; nf < 4; ++nf) {
      const int col = n0 + wn + nf * 8 + tg * 2;
      float2 v0 = make_float2(acc[mf][nf][0] + bv[nf].x, acc[mf][nf][1] + bv[nf].y);
      float2 v1 = make_float2(acc[mf][nf][2] + bv[nf].x, acc[mf][nf][3] + bv[nf].y);
      *(float2*)(g_xw + (size_t)row0 * G4 + col) = v0;
      *(float2*)(g_xw + (size_t)(row0 + 8) * G4 + col) = v1;
    }
  }
}

// ---------------------------------------------------------------------------
// Persistent TENSOR-CORE recurrence. 128 CTAs x 128 thr, grid barrier/step.
// CTA c owns h-cols [4c,4c+4) -> 16 gate-cols; n_local = i*4 + gate.
// Warp w computes m16(rows 16w..16w+15) x n16 over K=512 with m16n8k8 tf32.
// ---------------------------------------------------------------------------
#define RGRID    128
#define RTHREADS 128
#define ASTR 516   // a stage row stride (floats)
#define GSTR 20    // gate tile row stride

__device__ __forceinline__ float sigmoidf_(float x) {
  return 1.0f / (1.0f + __expf(-x));
}

__global__ __launch_bounds__(RTHREADS) void recur_tc_kernel(
    const float* __restrict__ U, float* __restrict__ out) {
  extern __shared__ float sm[];
  float* As = sm;                          // 64 x ASTR
  float* Us = sm + 64 * ASTR;              // 16 x ASTR
  float* Gs = sm + 64 * ASTR + 16 * ASTR;  // 64 x GSTR

  const int tid = threadIdx.x;
  const int lane = tid & 31, wid = tid >> 5;
  const int g = lane >> 2, tg = lane & 3;
  const int hb = blockIdx.x * 4;

  // --- preload U slice (tf32-rounded): Us[i*4+gate][k] = U[k][gate*512+hb+i]
  for (int idx = tid; idx < 4 * 512; idx += RTHREADS) {
    const int gate = idx & 3, k = idx >> 2;
    float4 v = *(const float4*)(U + (size_t)k * G4 + gate * HID + hb);
    Us[(0 * 4 + gate) * ASTR + k] = f2tf32f(v.x);
    Us[(1 * 4 + gate) * ASTR + k] = f2tf32f(v.y);
    Us[(2 * 4 + gate) * ASTR + k] = f2tf32f(v.z);
    Us[(3 * 4 + gate) * ASTR + k] = f2tf32f(v.w);
  }

  // per-thread constant indexing
  const int r0 = wid * 16 + g;             // acc row 0 (b)
  // xw global cols for acc regs: n_local = nf*8 + 2tg (+1)
  int colA[2], colB[2];
#pragma unroll
  for (int nf = 0; nf < 2; ++nf) {
    const int nlA = nf * 8 + 2 * tg, nlB = nlA + 1;
    colA[nf] = (nlA & 3) * HID + hb + (nlA >> 2);
    colB[nf] = (nlB & 3) * HID + hb + (nlB >> 2);
  }
  const int gb = tid >> 1;                 // gate-phase b
  const int gi0 = (tid & 1) * 2;           // gate-phase i base

  unsigned target = 0;

  for (int t = 0; t < T_STEPS; ++t) {
    // --- acc init = xw slice (DRAM; issue early)
    const float* xwp = g_xw + (size_t)t * BATCH * G4;
    float acc[2][4];
#pragma unroll
    for (int nf = 0; nf < 2; ++nf) {
      acc[nf][0] = __ldg(xwp + (size_t)r0 * G4 + colA[nf]);
      acc[nf][1] = __ldg(xwp + (size_t)r0 * G4 + colB[nf]);
      acc[nf][2] = __ldg(xwp + (size_t)(r0 + 8) * G4 + colA[nf]);
      acc[nf][3] = __ldg(xwp + (size_t)(r0 + 8) * G4 + colB[nf]);
    }

    // --- stage a_{t-1} (already tf32-rounded) into smem
    const float* src = g_atf[t & 1];
#pragma unroll 8
    for (int idx = tid; idx < BATCH * (HID / 4); idx += RTHREADS) {
      const int b = idx >> 7, k4 = idx & 127;
      float4 v = __ldcg((const float4*)(src + b * HID + k4 * 4));
      *(float4*)(As + b * ASTR + k4 * 4) = v;
    }
    __syncthreads();

    // --- mma over K=512: warp w does rows [16w,16w+16) x n_local [0,16)
    const float* Ab = As + (wid * 16) * ASTR;
#pragma unroll 4
    for (int k8 = 0; k8 < 64; ++k8) {
      const int kb = k8 * 8;
      uint32_t afr[4];
      afr[0] = __float_as_uint(Ab[g * ASTR + kb + tg]);
      afr[1] = __float_as_uint(Ab[(8 + g) * ASTR + kb + tg]);
      afr[2] = __float_as_uint(Ab[g * ASTR + kb + tg + 4]);
      afr[3] = __float_as_uint(Ab[(8 + g) * ASTR + kb + tg + 4]);
#pragma unroll
      for (int nf = 0; nf < 2; ++nf) {
        uint32_t bfr[2];
        const float* bp = Us + (nf * 8 + g) * ASTR + kb;
        bfr[0] = __float_as_uint(bp[tg]);
        bfr[1] = __float_as_uint(bp[tg + 4]);
        mma_tf32(acc[nf], afr, bfr);
      }
    }

    // --- scatter gate preactivations to Gs
#pragma unroll
    for (int nf = 0; nf < 2; ++nf) {
      *(float2*)(Gs + r0 * GSTR + nf * 8 + 2 * tg) =
          make_float2(acc[nf][0], acc[nf][1]);
      *(float2*)(Gs + (r0 + 8) * GSTR + nf * 8 + 2 * tg) =
          make_float2(acc[nf][2], acc[nf][3]);
    }
    __syncthreads();

    // --- gate math: thread handles (b=gb, i = gi0, gi0+1)
    float* dstE = out + (size_t)t * BATCH * HID;
    float* dstR = g_atf[(t + 1) & 1];
#pragma unroll
    for (int ii = 0; ii < 2; ++ii) {
      const int i = gi0 + ii;
      float4 gg = *(const float4*)(Gs + gb * GSTR + i * 4);
      const float gu = sigmoidf_(gg.x);
      const float gf = sigmoidf_(gg.y);
      const float go = sigmoidf_(gg.z);
      const float cd = tanhf(gg.w);
      const float ap = As[gb * ASTR + hb + i];  // tf32-rounded a_{t-1}
      const float ct = gu * cd + gf * ap;
      const float at = go * tanhf(ct);
      dstE[gb * HID + hb + i] = at;
      dstR[gb * HID + hb + i] = f2tf32f(at);
    }

    // --- grid barrier
    if (t + 1 < T_STEPS) {
      target += RGRID;
      __threadfence();
      __syncthreads();
      if (tid == 0) {
        atomicAdd(&g_bar, 1u);
        while (*(volatile unsigned*)&g_bar < target) { __nanosleep(32); }
        __threadfence();
      }
      __syncthreads();
    }
  }
}

// ---------------------------------------------------------------------------
extern "C" void kernel_launch(void* const* d_in, const int* in_sizes, int n_in,
                              void* d_out, int out_size) {
  (void)in_sizes; (void)n_in; (void)out_size;
  const float* x    = (const float*)d_in[0];  // [T, B, I]
  const float* a0   = (const float*)d_in[1];  // [B, H]
  const float* W    = (const float*)d_in[2];  // [I, 4H]
  const float* U    = (const float*)d_in[3];  // [H, 4H]
  const float* bias = (const float*)d_in[4];  // [4H]
  float* out = (float*)d_out;                 // [T, B, H]

  const int smemG = 4 * BM * SSTR * sizeof(float);  // 73728 B
  cudaFuncSetAttribute(xw_tc_kernel, cudaFuncAttributeMaxDynamicSharedMemorySize,
                       smemG);
  const int smemR = (64 * ASTR + 16 * ASTR + 64 * GSTR) * sizeof(float);  // 170240
  cudaFuncSetAttribute(recur_tc_kernel, cudaFuncAttributeMaxDynamicSharedMemorySize,
                       smemR);

  transpose_kernel<<<dim3(G4 / 32, INDIM / 32), dim3(32, 8)>>>(W, a0);
  xw_tc_kernel<<<dim3(G4 / BN, (T_STEPS * BATCH) / BM), 256, smemG>>>(x, bias);
  recur_tc_kernel<<<RGRID, RTHREADS, smemR>>>(U, out);
}

// round 5
// speedup vs baseline: 1.9856x; 1.4055x over previous
#include <cuda_runtime.h>
#include <cstdint>
#include <cstddef>

#define T_STEPS 512
#define BATCH   64
#define INDIM   512
#define HID     512
#define G4      2048   // 4*HID

// scratch: precomputed x@W+b, transposed tf32 W, ping-pong tf32 hidden state
__device__ float g_xw[(size_t)T_STEPS * BATCH * G4];
__device__ float g_Wt[(size_t)G4 * INDIM];
__device__ float g_atf[2][BATCH * HID];
__device__ unsigned g_bar;

__device__ __forceinline__ uint32_t f2tf32(float f) {
  uint32_t r;
  asm("cvt.rna.tf32.f32 %0, %1;" : "=r"(r) : "f"(f));
  return r;
}
__device__ __forceinline__ float f2tf32f(float f) {
  return __uint_as_float(f2tf32(f));
}

__device__ __forceinline__ void mma_tf32(float* d, const uint32_t* a,
                                         const uint32_t* b) {
  asm volatile(
      "mma.sync.aligned.m16n8k8.row.col.f32.tf32.tf32.f32 "
      "{%0,%1,%2,%3}, {%4,%5,%6,%7}, {%8,%9}, {%0,%1,%2,%3};"
      : "+f"(d[0]), "+f"(d[1]), "+f"(d[2]), "+f"(d[3])
      : "r"(a[0]), "r"(a[1]), "r"(a[2]), "r"(a[3]), "r"(b[0]), "r"(b[1]));
}

// ---------------------------------------------------------------------------
// W transpose + tf32 rounding; also rounds a0 into g_atf[0]; resets barrier.
// ---------------------------------------------------------------------------
__global__ __launch_bounds__(256) void transpose_kernel(const float* __restrict__ W,
                                                        const float* __restrict__ a0) {
  __shared__ float tile[32][33];
  const int n0 = blockIdx.x * 32, k0 = blockIdx.y * 32;
  const int tx = threadIdx.x, ty = threadIdx.y;  // 32 x 8
#pragma unroll
  for (int i = 0; i < 32; i += 8)
    tile[ty + i][tx] = W[(size_t)(k0 + ty + i) * G4 + n0 + tx];
  __syncthreads();
#pragma unroll
  for (int i = 0; i < 32; i += 8)
    g_Wt[(size_t)(n0 + ty + i) * INDIM + k0 + tx] = f2tf32f(tile[tx][ty + i]);
  if (blockIdx.y == 0) {  // 64 blocks x 256 thr: round a0 (32768 elems)
    const int fl = blockIdx.x * 256 + ty * 32 + tx;
    g_atf[0][fl] = f2tf32f(a0[fl]);
    g_atf[0][fl + 16384] = f2tf32f(a0[fl + 16384]);
  }
  if (blockIdx.x == 0 && blockIdx.y == 0 && tx == 0 && ty == 0) g_bar = 0u;
}

// ---------------------------------------------------------------------------
// TF32 tensor-core GEMM (unchanged, known-good): g_xw = x@W + bias
// ---------------------------------------------------------------------------
#define BM 128
#define BN 128
#define BK 32
#define SSTR 36

__global__ __launch_bounds__(256) void xw_tc_kernel(const float* __restrict__ A,
                                                    const float* __restrict__ bias) {
  extern __shared__ float smem[];
  float* As[2] = {smem, smem + BM * SSTR};
  float* Bs[2] = {smem + 2 * BM * SSTR, smem + 3 * BM * SSTR};

  const int tid = threadIdx.x;
  const int lane = tid & 31, wid = tid >> 5;
  const int wm = (wid >> 2) * 64;
  const int wn = (wid & 3) * 32;
  const int g = lane >> 2, tg = lane & 3;
  const int n0 = blockIdx.x * BN;
  const int m0 = blockIdx.y * BM;

  const int lr = tid >> 3;
  const int lc = (tid & 7) * 4;

  float acc[4][4][4];
#pragma unroll
  for (int i = 0; i < 4; ++i)
#pragma unroll
    for (int j = 0; j < 4; ++j)
#pragma unroll
      for (int q = 0; q < 4; ++q) acc[i][j][q] = 0.0f;

  float4 pa[4], pb[4];
#pragma unroll
  for (int j = 0; j < 4; ++j) {
    const int r = lr + j * 32;
    pa[j] = *(const float4*)(A + (size_t)(m0 + r) * INDIM + lc);
    pb[j] = *(const float4*)(g_Wt + (size_t)(n0 + r) * INDIM + lc);
  }

  const int NKT = INDIM / BK;  // 16
  for (int kt = 0; kt < NKT; ++kt) {
    const int s = kt & 1;
#pragma unroll
    for (int j = 0; j < 4; ++j) {
      const int r = lr + j * 32;
      float* ap = As[s] + r * SSTR + lc;
      ap[0] = f2tf32f(pa[j].x);
      ap[1] = f2tf32f(pa[j].y);
      ap[2] = f2tf32f(pa[j].z);
      ap[3] = f2tf32f(pa[j].w);
      *(float4*)(Bs[s] + r * SSTR + lc) = pb[j];
    }
    __syncthreads();

    if (kt + 1 < NKT) {
      const int ko = (kt + 1) * BK;
#pragma unroll
      for (int j = 0; j < 4; ++j) {
        const int r = lr + j * 32;
        pa[j] = *(const float4*)(A + (size_t)(m0 + r) * INDIM + ko + lc);
        pb[j] = *(const float4*)(g_Wt + (size_t)(n0 + r) * INDIM + ko + lc);
      }
    }

#pragma unroll
    for (int k8 = 0; k8 < 4; ++k8) {
      const int kb = k8 * 8;
      uint32_t afr[4][4], bfr[4][2];
#pragma unroll
      for (int mf = 0; mf < 4; ++mf) {
        const float* ap = As[s] + (wm + mf * 16) * SSTR + kb;
        afr[mf][0] = __float_as_uint(ap[g * SSTR + tg]);
        afr[mf][1] = __float_as_uint(ap[(g + 8) * SSTR + tg]);
        afr[mf][2] = __float_as_uint(ap[g * SSTR + tg + 4]);
        afr[mf][3] = __float_as_uint(ap[(g + 8) * SSTR + tg + 4]);
      }
#pragma unroll
      for (int nf = 0; nf < 4; ++nf) {
        const float* bp = Bs[s] + (wn + nf * 8) * SSTR + kb;
        bfr[nf][0] = __float_as_uint(bp[g * SSTR + tg]);
        bfr[nf][1] = __float_as_uint(bp[g * SSTR + tg + 4]);
      }
#pragma unroll
      for (int mf = 0; mf < 4; ++mf)
#pragma unroll
        for (int nf = 0; nf < 4; ++nf)
          mma_tf32(acc[mf][nf], afr[mf], bfr[nf]);
    }
    __syncthreads();
  }

  float2 bv[4];
#pragma unroll
  for (int nf = 0; nf < 4; ++nf)
    bv[nf] = *(const float2*)(bias + n0 + wn + nf * 8 + tg * 2);
#pragma unroll
  for (int mf = 0; mf < 4; ++mf) {
    const int row0 = m0 + wm + mf * 16 + g;
#pragma unroll
    for (int nf = 0; nf < 4; ++nf) {
      const int col = n0 + wn + nf * 8 + tg * 2;
      float2 v0 = make_float2(acc[mf][nf][0] + bv[nf].x, acc[mf][nf][1] + bv[nf].y);
      float2 v1 = make_float2(acc[mf][nf][2] + bv[nf].x, acc[mf][nf][3] + bv[nf].y);
      *(float2*)(g_xw + (size_t)row0 * G4 + col) = v0;
      *(float2*)(g_xw + (size_t)(row0 + 8) * G4 + col) = v1;
    }
  }
}

// ---------------------------------------------------------------------------
// Persistent TENSOR-CORE recurrence, 256 threads (2 warps/SMSP).
// CTA c owns h-cols [4c,4c+4) -> 16 gate-cols; n_local = i*4 + gate.
// Warp w: rows [16*(w&3), +16), K-half (w>>2)*256. Partial sums meet in Gs.
// ---------------------------------------------------------------------------
#define RGRID    128
#define RTHREADS 256
#define ASTR 516   // a stage row stride (floats)
#define GSTR 20    // gate tile row stride

__device__ __forceinline__ float sigmoidf_(float x) {
  return 1.0f / (1.0f + __expf(-x));
}

__global__ __launch_bounds__(RTHREADS) void recur_tc_kernel(
    const float* __restrict__ U, float* __restrict__ out) {
  extern __shared__ float sm[];
  float* As = sm;                          // 64 x ASTR
  float* Us = sm + 64 * ASTR;              // 16 x ASTR
  float* Gs = sm + 64 * ASTR + 16 * ASTR;  // 2 x 64 x GSTR

  const int tid = threadIdx.x;
  const int lane = tid & 31, wid = tid >> 5;
  const int g = lane >> 2, tg = lane & 3;
  const int kw = wid >> 2;                 // K-half
  const int wm = (wid & 3) * 16;           // batch-row base
  const int kb0 = kw * 256;
  const int hb = blockIdx.x * 4;

  // --- preload U slice (tf32-rounded): Us[i*4+gate][k] = U[k][gate*512+hb+i]
  for (int idx = tid; idx < 4 * 512; idx += RTHREADS) {
    const int gate = idx & 3, k = idx >> 2;
    float4 v = *(const float4*)(U + (size_t)k * G4 + gate * HID + hb);
    Us[(0 * 4 + gate) * ASTR + k] = f2tf32f(v.x);
    Us[(1 * 4 + gate) * ASTR + k] = f2tf32f(v.y);
    Us[(2 * 4 + gate) * ASTR + k] = f2tf32f(v.z);
    Us[(3 * 4 + gate) * ASTR + k] = f2tf32f(v.w);
  }

  const int r0 = wm + g;                   // acc row 0 (b)
  int colA[2], colB[2];
#pragma unroll
  for (int nf = 0; nf < 2; ++nf) {
    const int nlA = nf * 8 + 2 * tg, nlB = nlA + 1;
    colA[nf] = (nlA & 3) * HID + hb + (nlA >> 2);
    colB[nf] = (nlB & 3) * HID + hb + (nlB >> 2);
  }
  const int gb = tid >> 2;                 // gate-phase b (0..63)
  const int gi = tid & 3;                  // gate-phase i (0..3)

  // --- prefetch xw for t=0 (K-half-0 warps only)
  float pxw[8];
  if (kw == 0) {
    const float* xwp = g_xw;
#pragma unroll
    for (int nf = 0; nf < 2; ++nf) {
      pxw[nf * 4 + 0] = __ldg(xwp + (size_t)r0 * G4 + colA[nf]);
      pxw[nf * 4 + 1] = __ldg(xwp + (size_t)r0 * G4 + colB[nf]);
      pxw[nf * 4 + 2] = __ldg(xwp + (size_t)(r0 + 8) * G4 + colA[nf]);
      pxw[nf * 4 + 3] = __ldg(xwp + (size_t)(r0 + 8) * G4 + colB[nf]);
    }
  }

  unsigned target = 0;

  for (int t = 0; t < T_STEPS; ++t) {
    // --- acc init: xw (prefetched) for K-half 0, zero for K-half 1
    float acc[2][4];
#pragma unroll
    for (int nf = 0; nf < 2; ++nf)
#pragma unroll
      for (int q = 0; q < 4; ++q)
        acc[nf][q] = (kw == 0) ? pxw[nf * 4 + q] : 0.0f;

    // --- stage a_{t-1} (tf32-rounded) into smem: 8192 float4 over 256 thr
    const float* src = g_atf[t & 1];
#pragma unroll 8
    for (int idx = tid; idx < BATCH * (HID / 4); idx += RTHREADS) {
      const int b = idx >> 7, k4 = idx & 127;
      float4 v = __ldcg((const float4*)(src + b * HID + k4 * 4));
      *(float4*)(As + b * ASTR + k4 * 4) = v;
    }
    __syncthreads();

    // --- prefetch next step's xw while mma runs (hides DRAM latency)
    if (kw == 0 && t + 1 < T_STEPS) {
      const float* xwp = g_xw + (size_t)(t + 1) * BATCH * G4;
#pragma unroll
      for (int nf = 0; nf < 2; ++nf) {
        pxw[nf * 4 + 0] = __ldg(xwp + (size_t)r0 * G4 + colA[nf]);
        pxw[nf * 4 + 1] = __ldg(xwp + (size_t)r0 * G4 + colB[nf]);
        pxw[nf * 4 + 2] = __ldg(xwp + (size_t)(r0 + 8) * G4 + colA[nf]);
        pxw[nf * 4 + 3] = __ldg(xwp + (size_t)(r0 + 8) * G4 + colB[nf]);
      }
    }

    // --- mma over this warp's K-half (32 k8-iters)
    const float* Ab = As + wm * ASTR + kb0;
    const float* Ub0 = Us + (0 * 8 + g) * ASTR + kb0;
    const float* Ub1 = Us + (1 * 8 + g) * ASTR + kb0;
#pragma unroll 8
    for (int k8 = 0; k8 < 32; ++k8) {
      const int kb = k8 * 8;
      uint32_t afr[4];
      afr[0] = __float_as_uint(Ab[g * ASTR + kb + tg]);
      afr[1] = __float_as_uint(Ab[(8 + g) * ASTR + kb + tg]);
      afr[2] = __float_as_uint(Ab[g * ASTR + kb + tg + 4]);
      afr[3] = __float_as_uint(Ab[(8 + g) * ASTR + kb + tg + 4]);
      uint32_t bfr0[2], bfr1[2];
      bfr0[0] = __float_as_uint(Ub0[kb + tg]);
      bfr0[1] = __float_as_uint(Ub0[kb + tg + 4]);
      bfr1[0] = __float_as_uint(Ub1[kb + tg]);
      bfr1[1] = __float_as_uint(Ub1[kb + tg + 4]);
      mma_tf32(acc[0], afr, bfr0);
      mma_tf32(acc[1], afr, bfr1);
    }

    // --- scatter partial gate preactivations (per K-half region)
    float* Gsw = Gs + kw * 64 * GSTR;
#pragma unroll
    for (int nf = 0; nf < 2; ++nf) {
      *(float2*)(Gsw + r0 * GSTR + nf * 8 + 2 * tg) =
          make_float2(acc[nf][0], acc[nf][1]);
      *(float2*)(Gsw + (r0 + 8) * GSTR + nf * 8 + 2 * tg) =
          make_float2(acc[nf][2], acc[nf][3]);
    }
    __syncthreads();

    // --- gate math: 1 output per thread (b=gb, i=gi); sum the two K-halves
    {
      float4 gA = *(const float4*)(Gs + gb * GSTR + gi * 4);
      float4 gB = *(const float4*)(Gs + 64 * GSTR + gb * GSTR + gi * 4);
      const float gu = sigmoidf_(gA.x + gB.x);
      const float gf = sigmoidf_(gA.y + gB.y);
      const float go = sigmoidf_(gA.z + gB.z);
      const float cd = tanhf(gA.w + gB.w);
      const float ap = As[gb * ASTR + hb + gi];  // tf32-rounded a_{t-1}
      const float ct = gu * cd + gf * ap;
      const float at = go * tanhf(ct);
      out[(size_t)t * BATCH * HID + gb * HID + hb + gi] = at;
      g_atf[(t + 1) & 1][gb * HID + hb + gi] = f2tf32f(at);
    }

    // --- grid barrier
    if (t + 1 < T_STEPS) {
      target += RGRID;
      __threadfence();
      __syncthreads();
      if (tid == 0) {
        atomicAdd(&g_bar, 1u);
        while (*(volatile unsigned*)&g_bar < target) { __nanosleep(32); }
        __threadfence();
      }
      __syncthreads();
    }
  }
}

// ---------------------------------------------------------------------------
extern "C" void kernel_launch(void* const* d_in, const int* in_sizes, int n_in,
                              void* d_out, int out_size) {
  (void)in_sizes; (void)n_in; (void)out_size;
  const float* x    = (const float*)d_in[0];  // [T, B, I]
  const float* a0   = (const float*)d_in[1];  // [B, H]
  const float* W    = (const float*)d_in[2];  // [I, 4H]
  const float* U    = (const float*)d_in[3];  // [H, 4H]
  const float* bias = (const float*)d_in[4];  // [4H]
  float* out = (float*)d_out;                 // [T, B, H]

  const int smemG = 4 * BM * SSTR * sizeof(float);  // 73728 B
  cudaFuncSetAttribute(xw_tc_kernel, cudaFuncAttributeMaxDynamicSharedMemorySize,
                       smemG);
  const int smemR = (64 * ASTR + 16 * ASTR + 2 * 64 * GSTR) * sizeof(float);
  cudaFuncSetAttribute(recur_tc_kernel, cudaFuncAttributeMaxDynamicSharedMemorySize,
                       smemR);

  transpose_kernel<<<dim3(G4 / 32, INDIM / 32), dim3(32, 8)>>>(W, a0);
  xw_tc_kernel<<<dim3(G4 / BN, (T_STEPS * BATCH) / BM), 256, smemG>>>(x, bias);
  recur_tc_kernel<<<RGRID, RTHREADS, smemR>>>(U, out);
}

// round 6
// speedup vs baseline: 2.2819x; 1.1492x over previous
#include <cuda_runtime.h>
#include <cstdint>
#include <cstddef>

#define T_STEPS 512
#define BATCH   64
#define INDIM   512
#define HID     512
#define G4      2048   // 4*HID

// scratch: precomputed x@W+b, transposed tf32 W, ping-pong tf32 hidden state
__device__ float g_xw[(size_t)T_STEPS * BATCH * G4];
__device__ float g_Wt[(size_t)G4 * INDIM];
__device__ float g_atf[2][BATCH * HID];
#define NGROUPS 4
__device__ unsigned g_bars[NGROUPS * 32];   // one counter per 128B line

__device__ __forceinline__ uint32_t f2tf32(float f) {
  uint32_t r;
  asm("cvt.rna.tf32.f32 %0, %1;" : "=r"(r) : "f"(f));
  return r;
}
__device__ __forceinline__ float f2tf32f(float f) {
  return __uint_as_float(f2tf32(f));
}

__device__ __forceinline__ void mma_tf32(float* d, const uint32_t* a,
                                         const uint32_t* b) {
  asm volatile(
      "mma.sync.aligned.m16n8k8.row.col.f32.tf32.tf32.f32 "
      "{%0,%1,%2,%3}, {%4,%5,%6,%7}, {%8,%9}, {%0,%1,%2,%3};"
      : "+f"(d[0]), "+f"(d[1]), "+f"(d[2]), "+f"(d[3])
      : "r"(a[0]), "r"(a[1]), "r"(a[2]), "r"(a[3]), "r"(b[0]), "r"(b[1]));
}

// ---------------------------------------------------------------------------
// W transpose + tf32 rounding; rounds a0 into g_atf[0]; resets group barriers.
// ---------------------------------------------------------------------------
__global__ __launch_bounds__(256) void transpose_kernel(const float* __restrict__ W,
                                                        const float* __restrict__ a0) {
  __shared__ float tile[32][33];
  const int n0 = blockIdx.x * 32, k0 = blockIdx.y * 32;
  const int tx = threadIdx.x, ty = threadIdx.y;  // 32 x 8
#pragma unroll
  for (int i = 0; i < 32; i += 8)
    tile[ty + i][tx] = W[(size_t)(k0 + ty + i) * G4 + n0 + tx];
  __syncthreads();
#pragma unroll
  for (int i = 0; i < 32; i += 8)
    g_Wt[(size_t)(n0 + ty + i) * INDIM + k0 + tx] = f2tf32f(tile[tx][ty + i]);
  if (blockIdx.y == 0) {  // 64 blocks x 256 thr: round a0 (32768 elems)
    const int fl = blockIdx.x * 256 + ty * 32 + tx;
    g_atf[0][fl] = f2tf32f(a0[fl]);
    g_atf[0][fl + 16384] = f2tf32f(a0[fl + 16384]);
  }
  if (blockIdx.x == 0 && blockIdx.y == 0 && ty == 0 && tx < NGROUPS)
    g_bars[tx * 32] = 0u;
}

// ---------------------------------------------------------------------------
// TF32 tensor-core GEMM (unchanged, known-good): g_xw = x@W + bias
// ---------------------------------------------------------------------------
#define BM 128
#define BN 128
#define BK 32
#define SSTR 36

__global__ __launch_bounds__(256) void xw_tc_kernel(const float* __restrict__ A,
                                                    const float* __restrict__ bias) {
  extern __shared__ float smem[];
  float* As[2] = {smem, smem + BM * SSTR};
  float* Bs[2] = {smem + 2 * BM * SSTR, smem + 3 * BM * SSTR};

  const int tid = threadIdx.x;
  const int lane = tid & 31, wid = tid >> 5;
  const int wm = (wid >> 2) * 64;
  const int wn = (wid & 3) * 32;
  const int g = lane >> 2, tg = lane & 3;
  const int n0 = blockIdx.x * BN;
  const int m0 = blockIdx.y * BM;

  const int lr = tid >> 3;
  const int lc = (tid & 7) * 4;

  float acc[4][4][4];
#pragma unroll
  for (int i = 0; i < 4; ++i)
#pragma unroll
    for (int j = 0; j < 4; ++j)
#pragma unroll
      for (int q = 0; q < 4; ++q) acc[i][j][q] = 0.0f;

  float4 pa[4], pb[4];
#pragma unroll
  for (int j = 0; j < 4; ++j) {
    const int r = lr + j * 32;
    pa[j] = *(const float4*)(A + (size_t)(m0 + r) * INDIM + lc);
    pb[j] = *(const float4*)(g_Wt + (size_t)(n0 + r) * INDIM + lc);
  }

  const int NKT = INDIM / BK;  // 16
  for (int kt = 0; kt < NKT; ++kt) {
    const int s = kt & 1;
#pragma unroll
    for (int j = 0; j < 4; ++j) {
      const int r = lr + j * 32;
      float* ap = As[s] + r * SSTR + lc;
      ap[0] = f2tf32f(pa[j].x);
      ap[1] = f2tf32f(pa[j].y);
      ap[2] = f2tf32f(pa[j].z);
      ap[3] = f2tf32f(pa[j].w);
      *(float4*)(Bs[s] + r * SSTR + lc) = pb[j];
    }
    __syncthreads();

    if (kt + 1 < NKT) {
      const int ko = (kt + 1) * BK;
#pragma unroll
      for (int j = 0; j < 4; ++j) {
        const int r = lr + j * 32;
        pa[j] = *(const float4*)(A + (size_t)(m0 + r) * INDIM + ko + lc);
        pb[j] = *(const float4*)(g_Wt + (size_t)(n0 + r) * INDIM + ko + lc);
      }
    }

#pragma unroll
    for (int k8 = 0; k8 < 4; ++k8) {
      const int kb = k8 * 8;
      uint32_t afr[4][4], bfr[4][2];
#pragma unroll
      for (int mf = 0; mf < 4; ++mf) {
        const float* ap = As[s] + (wm + mf * 16) * SSTR + kb;
        afr[mf][0] = __float_as_uint(ap[g * SSTR + tg]);
        afr[mf][1] = __float_as_uint(ap[(g + 8) * SSTR + tg]);
        afr[mf][2] = __float_as_uint(ap[g * SSTR + tg + 4]);
        afr[mf][3] = __float_as_uint(ap[(g + 8) * SSTR + tg + 4]);
      }
#pragma unroll
      for (int nf = 0; nf < 4; ++nf) {
        const float* bp = Bs[s] + (wn + nf * 8) * SSTR + kb;
        bfr[nf][0] = __float_as_uint(bp[g * SSTR + tg]);
        bfr[nf][1] = __float_as_uint(bp[g * SSTR + tg + 4]);
      }
#pragma unroll
      for (int mf = 0; mf < 4; ++mf)
#pragma unroll
        for (int nf = 0; nf < 4; ++nf)
          mma_tf32(acc[mf][nf], afr[mf], bfr[nf]);
    }
    __syncthreads();
  }

  float2 bv[4];
#pragma unroll
  for (int nf = 0; nf < 4; ++nf)
    bv[nf] = *(const float2*)(bias + n0 + wn + nf * 8 + tg * 2);
#pragma unroll
  for (int mf = 0; mf < 4; ++mf) {
    const int row0 = m0 + wm + mf * 16 + g;
#pragma unroll
    for (int nf = 0; nf < 4; ++nf) {
      const int col = n0 + wn + nf * 8 + tg * 2;
      float2 v0 = make_float2(acc[mf][nf][0] + bv[nf].x, acc[mf][nf][1] + bv[nf].y);
      float2 v1 = make_float2(acc[mf][nf][2] + bv[nf].x, acc[mf][nf][3] + bv[nf].y);
      *(float2*)(g_xw + (size_t)row0 * G4 + col) = v0;
      *(float2*)(g_xw + (size_t)(row0 + 8) * G4 + col) = v1;
    }
  }
}

// ---------------------------------------------------------------------------
// Persistent TC recurrence, BATCH-SPLIT: 4 independent groups of 16 batch
// rows, 32 CTAs each (own grid barrier). CTA: m16 x n64 (16 h-cols) x K512.
// 8 warps = 4 n-quarters x 2 K-halves; partial sums meet in Gs.
// ---------------------------------------------------------------------------
#define GCTAS    32
#define GBATCH   16
#define RTHREADS 256
#define ASTR 516   // smem row stride (floats)
#define GSTR 68    // gate tile row stride (64 + 4 pad)

__device__ __forceinline__ float sigmoidf_(float x) {
  return 1.0f / (1.0f + __expf(-x));
}

__global__ __launch_bounds__(RTHREADS) void recur_tc_kernel(
    const float* __restrict__ U, float* __restrict__ out) {
  extern __shared__ float sm[];
  float* As = sm;                              // 16 x ASTR
  float* Us = sm + GBATCH * ASTR;              // 64 x ASTR
  float* Gs = sm + GBATCH * ASTR + 64 * ASTR;  // 2 x 16 x GSTR

  const int tid = threadIdx.x;
  const int lane = tid & 31, wid = tid >> 5;
  const int g = lane >> 2, tg = lane & 3;
  const int kw = wid >> 2;                 // K-half (0,1)
  const int nq = wid & 3;                  // n-quarter (0..3)
  const int kb0 = kw * 256;
  const int group = blockIdx.x >> 5;       // 0..3 (batch group)
  const int cg = blockIdx.x & 31;          // CTA in group
  const int hb = cg * 16;                  // h-col base (16 h per CTA)
  const int b0 = group * GBATCH;           // global batch base
  volatile unsigned* bar = &g_bars[group * 32];

  // --- preload U slice (tf32): Us[i*4+gate][k] = U[k][gate*512+hb+i], i<16
  for (int idx = tid; idx < 512 * 4 * 4; idx += RTHREADS) {
    const int k = idx >> 4, gate = (idx >> 2) & 3, iq = idx & 3;
    float4 v = *(const float4*)(U + (size_t)k * G4 + gate * HID + hb + iq * 4);
    Us[((iq * 4 + 0) * 4 + gate) * ASTR + k] = f2tf32f(v.x);
    Us[((iq * 4 + 1) * 4 + gate) * ASTR + k] = f2tf32f(v.y);
    Us[((iq * 4 + 2) * 4 + gate) * ASTR + k] = f2tf32f(v.z);
    Us[((iq * 4 + 3) * 4 + gate) * ASTR + k] = f2tf32f(v.w);
  }

  // acc columns in xw space: n_local = nq*16 + nf*8 + 2tg (+1)
  int colA[2], colB[2];
#pragma unroll
  for (int nf = 0; nf < 2; ++nf) {
    const int nlA = nq * 16 + nf * 8 + 2 * tg, nlB = nlA + 1;
    colA[nf] = (nlA & 3) * HID + hb + (nlA >> 2);
    colB[nf] = (nlB & 3) * HID + hb + (nlB >> 2);
  }
  const int bl = tid >> 4;                 // gate-phase local batch (0..15)
  const int hi = tid & 15;                 // gate-phase h index (0..15)

  // --- prefetch xw for t=0 (K-half-0 warps hold the init)
  float pxw[8];
  if (kw == 0) {
    const float* xwp = g_xw + (size_t)(b0 + g) * G4;
#pragma unroll
    for (int nf = 0; nf < 2; ++nf) {
      pxw[nf * 4 + 0] = __ldg(xwp + colA[nf]);
      pxw[nf * 4 + 1] = __ldg(xwp + colB[nf]);
      pxw[nf * 4 + 2] = __ldg(xwp + 8 * G4 + colA[nf]);
      pxw[nf * 4 + 3] = __ldg(xwp + 8 * G4 + colB[nf]);
    }
  }

  unsigned target = 0;

  for (int t = 0; t < T_STEPS; ++t) {
    // --- acc init
    float acc[2][4];
#pragma unroll
    for (int nf = 0; nf < 2; ++nf)
#pragma unroll
      for (int q = 0; q < 4; ++q)
        acc[nf][q] = (kw == 0) ? pxw[nf * 4 + q] : 0.0f;

    // --- stage this group's a_{t-1} rows (16 x 512, tf32-rounded already)
    const float* src = g_atf[t & 1] + (size_t)b0 * HID;
#pragma unroll
    for (int j = 0; j < 8; ++j) {
      const int idx = tid + j * RTHREADS;  // 0..2047
      const int b = idx >> 7, k4 = idx & 127;
      float4 v = __ldcg((const float4*)(src + b * HID + k4 * 4));
      *(float4*)(As + b * ASTR + k4 * 4) = v;
    }
    __syncthreads();

    // --- prefetch next step's xw while mma runs
    if (kw == 0 && t + 1 < T_STEPS) {
      const float* xwp = g_xw + (size_t)(t + 1) * BATCH * G4 + (size_t)(b0 + g) * G4;
#pragma unroll
      for (int nf = 0; nf < 2; ++nf) {
        pxw[nf * 4 + 0] = __ldg(xwp + colA[nf]);
        pxw[nf * 4 + 1] = __ldg(xwp + colB[nf]);
        pxw[nf * 4 + 2] = __ldg(xwp + 8 * G4 + colA[nf]);
        pxw[nf * 4 + 3] = __ldg(xwp + 8 * G4 + colB[nf]);
      }
    }

    // --- mma: m16 (all 16 rows) x n16 (quarter) over this warp's K-half
    const float* Ab = As + kb0;
    const float* Ub0 = Us + (nq * 16 + 0 * 8 + g) * ASTR + kb0;
    const float* Ub1 = Us + (nq * 16 + 1 * 8 + g) * ASTR + kb0;
#pragma unroll 8
    for (int k8 = 0; k8 < 32; ++k8) {
      const int kb = k8 * 8;
      uint32_t afr[4];
      afr[0] = __float_as_uint(Ab[g * ASTR + kb + tg]);
      afr[1] = __float_as_uint(Ab[(8 + g) * ASTR + kb + tg]);
      afr[2] = __float_as_uint(Ab[g * ASTR + kb + tg + 4]);
      afr[3] = __float_as_uint(Ab[(8 + g) * ASTR + kb + tg + 4]);
      uint32_t bfr0[2], bfr1[2];
      bfr0[0] = __float_as_uint(Ub0[kb + tg]);
      bfr0[1] = __float_as_uint(Ub0[kb + tg + 4]);
      bfr1[0] = __float_as_uint(Ub1[kb + tg]);
      bfr1[1] = __float_as_uint(Ub1[kb + tg + 4]);
      mma_tf32(acc[0], afr, bfr0);
      mma_tf32(acc[1], afr, bfr1);
    }

    // --- scatter partial preactivations (per K-half region)
    float* Gsw = Gs + kw * GBATCH * GSTR;
#pragma unroll
    for (int nf = 0; nf < 2; ++nf) {
      const int nb = nq * 16 + nf * 8 + 2 * tg;
      *(float2*)(Gsw + g * GSTR + nb) = make_float2(acc[nf][0], acc[nf][1]);
      *(float2*)(Gsw + (g + 8) * GSTR + nb) = make_float2(acc[nf][2], acc[nf][3]);
    }
    __syncthreads();

    // --- gate math: 1 output/thread (b=bl, h=hb+hi); sum the two K-halves
    {
      float4 gA = *(const float4*)(Gs + bl * GSTR + hi * 4);
      float4 gB = *(const float4*)(Gs + GBATCH * GSTR + bl * GSTR + hi * 4);
      const float gu = sigmoidf_(gA.x + gB.x);
      const float gf = sigmoidf_(gA.y + gB.y);
      const float go = sigmoidf_(gA.z + gB.z);
      const float cd = tanhf(gA.w + gB.w);
      const float ap = As[bl * ASTR + hb + hi];  // tf32-rounded a_{t-1}
      const float ct = gu * cd + gf * ap;
      const float at = go * tanhf(ct);
      out[(size_t)t * BATCH * HID + (size_t)(b0 + bl) * HID + hb + hi] = at;
      g_atf[(t + 1) & 1][(b0 + bl) * HID + hb + hi] = f2tf32f(at);
    }

    // --- per-group grid barrier (32 CTAs)
    if (t + 1 < T_STEPS) {
      target += GCTAS;
      __threadfence();
      __syncthreads();
      if (tid == 0) {
        atomicAdd((unsigned*)bar, 1u);
        while (*bar < target) { __nanosleep(32); }
        __threadfence();
      }
      __syncthreads();
    }
  }
}

// ---------------------------------------------------------------------------
extern "C" void kernel_launch(void* const* d_in, const int* in_sizes, int n_in,
                              void* d_out, int out_size) {
  (void)in_sizes; (void)n_in; (void)out_size;
  const float* x    = (const float*)d_in[0];  // [T, B, I]
  const float* a0   = (const float*)d_in[1];  // [B, H]
  const float* W    = (const float*)d_in[2];  // [I, 4H]
  const float* U    = (const float*)d_in[3];  // [H, 4H]
  const float* bias = (const float*)d_in[4];  // [4H]
  float* out = (float*)d_out;                 // [T, B, H]

  const int smemG = 4 * BM * SSTR * sizeof(float);  // 73728 B
  cudaFuncSetAttribute(xw_tc_kernel, cudaFuncAttributeMaxDynamicSharedMemorySize,
                       smemG);
  const int smemR =
      (GBATCH * ASTR + 64 * ASTR + 2 * GBATCH * GSTR) * sizeof(float);  // 173824
  cudaFuncSetAttribute(recur_tc_kernel, cudaFuncAttributeMaxDynamicSharedMemorySize,
                       smemR);

  transpose_kernel<<<dim3(G4 / 32, INDIM / 32), dim3(32, 8)>>>(W, a0);
  xw_tc_kernel<<<dim3(G4 / BN, (T_STEPS * BATCH) / BM), 256, smemG>>>(x, bias);
  recur_tc_kernel<<<NGROUPS * GCTAS, RTHREADS, smemR>>>(U, out);
}

// round 9
// speedup vs baseline: 3.4325x; 1.5043x over previous
#include <cuda_runtime.h>
#include <cstdint>
#include <cstddef>

#define T_STEPS 512
#define BATCH   64
#define INDIM   512
#define HID     512
#define G4      2048   // 4*HID

// scratch: precomputed x@W+b, transposed tf32 W, ping-pong tf32 hidden state
__device__ float g_xw[(size_t)T_STEPS * BATCH * G4];
__device__ float g_Wt[(size_t)G4 * INDIM];
__device__ float g_atf[2][BATCH * HID];
#define NGROUPS 4
#define GCTAS   32
// per-CTA barrier flags, each on its own 128B line: g_flags[group][cta*32]
__device__ unsigned g_flags[NGROUPS][GCTAS * 32];

__device__ __forceinline__ uint32_t f2tf32(float f) {
  uint32_t r;
  asm("cvt.rna.tf32.f32 %0, %1;" : "=r"(r) : "f"(f));
  return r;
}
__device__ __forceinline__ float f2tf32f(float f) {
  return __uint_as_float(f2tf32(f));
}

__device__ __forceinline__ void mma_tf32(float* d, const uint32_t* a,
                                         const uint32_t* b) {
  asm volatile(
      "mma.sync.aligned.m16n8k8.row.col.f32.tf32.tf32.f32 "
      "{%0,%1,%2,%3}, {%4,%5,%6,%7}, {%8,%9}, {%0,%1,%2,%3};"
      : "+f"(d[0]), "+f"(d[1]), "+f"(d[2]), "+f"(d[3])
      : "r"(a[0]), "r"(a[1]), "r"(a[2]), "r"(a[3]), "r"(b[0]), "r"(b[1]));
}

// ---------------------------------------------------------------------------
// W transpose + tf32 rounding; rounds a0 into g_atf[0]; zeroes barrier flags.
// ---------------------------------------------------------------------------
__global__ __launch_bounds__(256) void transpose_kernel(const float* __restrict__ W,
                                                        const float* __restrict__ a0) {
  __shared__ float tile[32][33];
  const int n0 = blockIdx.x * 32, k0 = blockIdx.y * 32;
  const int tx = threadIdx.x, ty = threadIdx.y;  // 32 x 8
#pragma unroll
  for (int i = 0; i < 32; i += 8)
    tile[ty + i][tx] = W[(size_t)(k0 + ty + i) * G4 + n0 + tx];
  __syncthreads();
#pragma unroll
  for (int i = 0; i < 32; i += 8)
    g_Wt[(size_t)(n0 + ty + i) * INDIM + k0 + tx] = f2tf32f(tile[tx][ty + i]);
  if (blockIdx.y == 0) {  // 64 blocks x 256 thr: round a0 (32768 elems)
    const int fl = blockIdx.x * 256 + ty * 32 + tx;
    g_atf[0][fl] = f2tf32f(a0[fl]);
    g_atf[0][fl + 16384] = f2tf32f(a0[fl + 16384]);
  }
  if (blockIdx.x == 0 && blockIdx.y == 0) {  // zero all flags (4096 u32)
    const int lt = ty * 32 + tx;
#pragma unroll
    for (int j = 0; j < NGROUPS * GCTAS * 32 / 256; ++j)
      ((unsigned*)g_flags)[lt + j * 256] = 0u;
  }
}

// ---------------------------------------------------------------------------
// TF32 tensor-core GEMM (unchanged, known-good): g_xw = x@W + bias
// ---------------------------------------------------------------------------
#define BM 128
#define BN 128
#define BK 32
#define SSTR 36

__global__ __launch_bounds__(256) void xw_tc_kernel(const float* __restrict__ A,
                                                    const float* __restrict__ bias) {
  extern __shared__ float smem[];
  float* As[2] = {smem, smem + BM * SSTR};
  float* Bs[2] = {smem + 2 * BM * SSTR, smem + 3 * BM * SSTR};

  const int tid = threadIdx.x;
  const int lane = tid & 31, wid = tid >> 5;
  const int wm = (wid >> 2) * 64;
  const int wn = (wid & 3) * 32;
  const int g = lane >> 2, tg = lane & 3;
  const int n0 = blockIdx.x * BN;
  const int m0 = blockIdx.y * BM;

  const int lr = tid >> 3;
  const int lc = (tid & 7) * 4;

  float acc[4][4][4];
#pragma unroll
  for (int i = 0; i < 4; ++i)
#pragma unroll
    for (int j = 0; j < 4; ++j)
#pragma unroll
      for (int q = 0; q < 4; ++q) acc[i][j][q] = 0.0f;

  float4 pa[4], pb[4];
#pragma unroll
  for (int j = 0; j < 4; ++j) {
    const int r = lr + j * 32;
    pa[j] = *(const float4*)(A + (size_t)(m0 + r) * INDIM + lc);
    pb[j] = *(const float4*)(g_Wt + (size_t)(n0 + r) * INDIM + lc);
  }

  const int NKT = INDIM / BK;  // 16
  for (int kt = 0; kt < NKT; ++kt) {
    const int s = kt & 1;
#pragma unroll
    for (int j = 0; j < 4; ++j) {
      const int r = lr + j * 32;
      float* ap = As[s] + r * SSTR + lc;
      ap[0] = f2tf32f(pa[j].x);
      ap[1] = f2tf32f(pa[j].y);
      ap[2] = f2tf32f(pa[j].z);
      ap[3] = f2tf32f(pa[j].w);
      *(float4*)(Bs[s] + r * SSTR + lc) = pb[j];
    }
    __syncthreads();

    if (kt + 1 < NKT) {
      const int ko = (kt + 1) * BK;
#pragma unroll
      for (int j = 0; j < 4; ++j) {
        const int r = lr + j * 32;
        pa[j] = *(const float4*)(A + (size_t)(m0 + r) * INDIM + ko + lc);
        pb[j] = *(const float4*)(g_Wt + (size_t)(n0 + r) * INDIM + ko + lc);
      }
    }

#pragma unroll
    for (int k8 = 0; k8 < 4; ++k8) {
      const int kb = k8 * 8;
      uint32_t afr[4][4], bfr[4][2];
#pragma unroll
      for (int mf = 0; mf < 4; ++mf) {
        const float* ap = As[s] + (wm + mf * 16) * SSTR + kb;
        afr[mf][0] = __float_as_uint(ap[g * SSTR + tg]);
        afr[mf][1] = __float_as_uint(ap[(g + 8) * SSTR + tg]);
        afr[mf][2] = __float_as_uint(ap[g * SSTR + tg + 4]);
        afr[mf][3] = __float_as_uint(ap[(g + 8) * SSTR + tg + 4]);
      }
#pragma unroll
      for (int nf = 0; nf < 4; ++nf) {
        const float* bp = Bs[s] + (wn + nf * 8) * SSTR + kb;
        bfr[nf][0] = __float_as_uint(bp[g * SSTR + tg]);
        bfr[nf][1] = __float_as_uint(bp[g * SSTR + tg + 4]);
      }
#pragma unroll
      for (int mf = 0; mf < 4; ++mf)
#pragma unroll
        for (int nf = 0; nf < 4; ++nf)
          mma_tf32(acc[mf][nf], afr[mf], bfr[nf]);
    }
    __syncthreads();
  }

  float2 bv[4];
#pragma unroll
  for (int nf = 0; nf < 4; ++nf)
    bv[nf] = *(const float2*)(bias + n0 + wn + nf * 8 + tg * 2);
#pragma unroll
  for (int mf = 0; mf < 4; ++mf) {
    const int row0 = m0 + wm + mf * 16 + g;
#pragma unroll
    for (int nf = 0; nf < 4; ++nf) {
      const int col = n0 + wn + nf * 8 + tg * 2;
      float2 v0 = make_float2(acc[mf][nf][0] + bv[nf].x, acc[mf][nf][1] + bv[nf].y);
      float2 v1 = make_float2(acc[mf][nf][2] + bv[nf].x, acc[mf][nf][3] + bv[nf].y);
      *(float2*)(g_xw + (size_t)row0 * G4 + col) = v0;
      *(float2*)(g_xw + (size_t)(row0 + 8) * G4 + col) = v1;
    }
  }
}

// ---------------------------------------------------------------------------
// Persistent TC recurrence, batch-split into 4 groups of 16 rows x 32 CTAs.
// Barrier = per-CTA release-flag + warp-parallel acquire polling (no fence,
// no atomics, no nanosleep).
// ---------------------------------------------------------------------------
#define GBATCH   16
#define RTHREADS 256
#define ASTR 516   // smem row stride (floats)
#define GSTR 68    // gate tile row stride (64 + 4 pad)

__device__ __forceinline__ float sigmoidf_(float x) {
  return 1.0f / (1.0f + __expf(-x));
}

__global__ __launch_bounds__(RTHREADS) void recur_tc_kernel(
    const float* __restrict__ U, float* __restrict__ out) {
  extern __shared__ float sm[];
  float* As = sm;                              // 16 x ASTR
  float* Us = sm + GBATCH * ASTR;              // 64 x ASTR
  float* Gs = sm + GBATCH * ASTR + 64 * ASTR;  // 2 x 16 x GSTR

  const int tid = threadIdx.x;
  const int lane = tid & 31, wid = tid >> 5;
  const int g = lane >> 2, tg = lane & 3;
  const int kw = wid >> 2;                 // K-half (0,1)
  const int nq = wid & 3;                  // n-quarter (0..3)
  const int kb0 = kw * 256;
  const int group = blockIdx.x >> 5;       // 0..3 (batch group)
  const int cg = blockIdx.x & 31;          // CTA in group
  const int hb = cg * 16;                  // h-col base (16 h per CTA)
  const int b0 = group * GBATCH;           // global batch base
  unsigned* myflag = &g_flags[group][cg * 32];
  unsigned* pollp = &g_flags[group][lane * 32];

  // --- preload U slice (tf32): Us[i*4+gate][k] = U[k][gate*512+hb+i], i<16
  for (int idx = tid; idx < 512 * 4 * 4; idx += RTHREADS) {
    const int k = idx >> 4, gate = (idx >> 2) & 3, iq = idx & 3;
    float4 v = *(const float4*)(U + (size_t)k * G4 + gate * HID + hb + iq * 4);
    Us[((iq * 4 + 0) * 4 + gate) * ASTR + k] = f2tf32f(v.x);
    Us[((iq * 4 + 1) * 4 + gate) * ASTR + k] = f2tf32f(v.y);
    Us[((iq * 4 + 2) * 4 + gate) * ASTR + k] = f2tf32f(v.z);
    Us[((iq * 4 + 3) * 4 + gate) * ASTR + k] = f2tf32f(v.w);
  }

  // acc columns in xw space: n_local = nq*16 + nf*8 + 2tg (+1)
  int colA[2], colB[2];
#pragma unroll
  for (int nf = 0; nf < 2; ++nf) {
    const int nlA = nq * 16 + nf * 8 + 2 * tg, nlB = nlA + 1;
    colA[nf] = (nlA & 3) * HID + hb + (nlA >> 2);
    colB[nf] = (nlB & 3) * HID + hb + (nlB >> 2);
  }
  const int bl = tid >> 4;                 // gate-phase local batch (0..15)
  const int hi = tid & 15;                 // gate-phase h index (0..15)

  // --- prefetch xw for t=0 (K-half-0 warps hold the init)
  float pxw[8];
  if (kw == 0) {
    const float* xwp = g_xw + (size_t)(b0 + g) * G4;
#pragma unroll
    for (int nf = 0; nf < 2; ++nf) {
      pxw[nf * 4 + 0] = __ldg(xwp + colA[nf]);
      pxw[nf * 4 + 1] = __ldg(xwp + colB[nf]);
      pxw[nf * 4 + 2] = __ldg(xwp + 8 * G4 + colA[nf]);
      pxw[nf * 4 + 3] = __ldg(xwp + 8 * G4 + colB[nf]);
    }
  }

  for (int t = 0; t < T_STEPS; ++t) {
    // --- acc init
    float acc[2][4];
#pragma unroll
    for (int nf = 0; nf < 2; ++nf)
#pragma unroll
      for (int q = 0; q < 4; ++q)
        acc[nf][q] = (kw == 0) ? pxw[nf * 4 + q] : 0.0f;

    // --- stage this group's a_{t-1} rows (16 x 512, tf32-rounded already)
    const float* src = g_atf[t & 1] + (size_t)b0 * HID;
#pragma unroll
    for (int j = 0; j < 8; ++j) {
      const int idx = tid + j * RTHREADS;  // 0..2047
      const int b = idx >> 7, k4 = idx & 127;
      float4 v = __ldcg((const float4*)(src + b * HID + k4 * 4));
      *(float4*)(As + b * ASTR + k4 * 4) = v;
    }
    __syncthreads();

    // --- prefetch next step's xw while mma runs
    if (kw == 0 && t + 1 < T_STEPS) {
      const float* xwp = g_xw + (size_t)(t + 1) * BATCH * G4 + (size_t)(b0 + g) * G4;
#pragma unroll
      for (int nf = 0; nf < 2; ++nf) {
        pxw[nf * 4 + 0] = __ldg(xwp + colA[nf]);
        pxw[nf * 4 + 1] = __ldg(xwp + colB[nf]);
        pxw[nf * 4 + 2] = __ldg(xwp + 8 * G4 + colA[nf]);
        pxw[nf * 4 + 3] = __ldg(xwp + 8 * G4 + colB[nf]);
      }
    }

    // --- mma: m16 (all 16 rows) x n16 (quarter) over this warp's K-half
    const float* Ab = As + kb0;
    const float* Ub0 = Us + (nq * 16 + 0 * 8 + g) * ASTR + kb0;
    const float* Ub1 = Us + (nq * 16 + 1 * 8 + g) * ASTR + kb0;
#pragma unroll 8
    for (int k8 = 0; k8 < 32; ++k8) {
      const int kb = k8 * 8;
      uint32_t afr[4];
      afr[0] = __float_as_uint(Ab[g * ASTR + kb + tg]);
      afr[1] = __float_as_uint(Ab[(8 + g) * ASTR + kb + tg]);
      afr[2] = __float_as_uint(Ab[g * ASTR + kb + tg + 4]);
      afr[3] = __float_as_uint(Ab[(8 + g) * ASTR + kb + tg + 4]);
      uint32_t bfr0[2], bfr1[2];
      bfr0[0] = __float_as_uint(Ub0[kb + tg]);
      bfr0[1] = __float_as_uint(Ub0[kb + tg + 4]);
      bfr1[0] = __float_as_uint(Ub1[kb + tg]);
      bfr1[1] = __float_as_uint(Ub1[kb + tg + 4]);
      mma_tf32(acc[0], afr, bfr0);
      mma_tf32(acc[1], afr, bfr1);
    }

    // --- scatter partial preactivations (per K-half region)
    float* Gsw = Gs + kw * GBATCH * GSTR;
#pragma unroll
    for (int nf = 0; nf < 2; ++nf) {
      const int nb = nq * 16 + nf * 8 + 2 * tg;
      *(float2*)(Gsw + g * GSTR + nb) = make_float2(acc[nf][0], acc[nf][1]);
      *(float2*)(Gsw + (g + 8) * GSTR + nb) = make_float2(acc[nf][2], acc[nf][3]);
    }
    __syncthreads();

    // --- gate math: 1 output/thread (b=bl, h=hb+hi); sum the two K-halves
    {
      float4 gA = *(const float4*)(Gs + bl * GSTR + hi * 4);
      float4 gB = *(const float4*)(Gs + GBATCH * GSTR + bl * GSTR + hi * 4);
      const float gu = sigmoidf_(gA.x + gB.x);
      const float gf = sigmoidf_(gA.y + gB.y);
      const float go = sigmoidf_(gA.z + gB.z);
      const float cd = tanhf(gA.w + gB.w);
      const float ap = As[bl * ASTR + hb + hi];  // tf32-rounded a_{t-1}
      const float ct = gu * cd + gf * ap;
      const float at = go * tanhf(ct);
      g_atf[(t + 1) & 1][(b0 + bl) * HID + hb + hi] = f2tf32f(at);
      out[(size_t)t * BATCH * HID + (size_t)(b0 + bl) * HID + hb + hi] = at;
    }

    // --- per-group barrier: release flag + warp-parallel acquire polling
    if (t + 1 < T_STEPS) {
      __syncthreads();  // all g_atf writes of this CTA issued before release
      if (tid == 0) {
        unsigned v = (unsigned)(t + 1);
        asm volatile("st.release.gpu.global.u32 [%0], %1;"
                     :: "l"(myflag), "r"(v) : "memory");
      }
      if (tid < 32) {
        const unsigned tgt = (unsigned)(t + 1);
        unsigned v;
        do {
          asm volatile("ld.acquire.gpu.global.u32 %0, [%1];"
                       : "=r"(v) : "l"(pollp) : "memory");
        } while (!__all_sync(0xFFFFFFFFu, v >= tgt));
      }
      __syncthreads();  // acquire ordering propagates to all warps
    }
  }
}

// ---------------------------------------------------------------------------
extern "C" void kernel_launch(void* const* d_in, const int* in_sizes, int n_in,
                              void* d_out, int out_size) {
  (void)in_sizes; (void)n_in; (void)out_size;
  const float* x    = (const float*)d_in[0];  // [T, B, I]
  const float* a0   = (const float*)d_in[1];  // [B, H]
  const float* W    = (const float*)d_in[2];  // [I, 4H]
  const float* U    = (const float*)d_in[3];  // [H, 4H]
  const float* bias = (const float*)d_in[4];  // [4H]
  float* out = (float*)d_out;                 // [T, B, H]

  const int smemG = 4 * BM * SSTR * sizeof(float);  // 73728 B
  cudaFuncSetAttribute(xw_tc_kernel, cudaFuncAttributeMaxDynamicSharedMemorySize,
                       smemG);
  const int smemR =
      (GBATCH * ASTR + 64 * ASTR + 2 * GBATCH * GSTR) * sizeof(float);  // 173824
  cudaFuncSetAttribute(recur_tc_kernel, cudaFuncAttributeMaxDynamicSharedMemorySize,
                       smemR);

  transpose_kernel<<<dim3(G4 / 32, INDIM / 32), dim3(32, 8)>>>(W, a0);
  xw_tc_kernel<<<dim3(G4 / BN, (T_STEPS * BATCH) / BM), 256, smemG>>>(x, bias);
  recur_tc_kernel<<<NGROUPS * GCTAS, RTHREADS, smemR>>>(U, out);
}

// round 12
// speedup vs baseline: 3.7027x; 1.0787x over previous
#include <cuda_runtime.h>
#include <cstdint>
#include <cstddef>

#define T_STEPS 512
#define BATCH   64
#define INDIM   512
#define HID     512
#define G4      2048   // 4*HID

// scratch: precomputed x@W+b, transposed tf32 W, ping-pong tf32 hidden state
__device__ float g_xw[(size_t)T_STEPS * BATCH * G4];
__device__ float g_Wt[(size_t)G4 * INDIM];
__device__ float g_atf[2][BATCH * HID];
#define NGROUPS 4
#define GCTAS   32
// per-CTA barrier flags, each on its own 128B line: g_flags[group][cta*32]
__device__ unsigned g_flags[NGROUPS][GCTAS * 32];

__device__ __forceinline__ uint32_t f2tf32(float f) {
  uint32_t r;
  asm("cvt.rna.tf32.f32 %0, %1;" : "=r"(r) : "f"(f));
  return r;
}
__device__ __forceinline__ float f2tf32f(float f) {
  return __uint_as_float(f2tf32(f));
}
__device__ __forceinline__ uint32_t smem_u32(const void* p) {
  uint32_t a;
  asm("{ .reg .u64 t; cvta.to.shared.u64 t, %1; cvt.u32.u64 %0, t; }"
      : "=r"(a) : "l"(p));
  return a;
}
__device__ __forceinline__ void ldsm_x4(uint32_t* d, uint32_t addr) {
  asm volatile("ldmatrix.sync.aligned.m8n8.x4.shared.b16 {%0,%1,%2,%3}, [%4];"
               : "=r"(d[0]), "=r"(d[1]), "=r"(d[2]), "=r"(d[3]) : "r"(addr));
}

__device__ __forceinline__ void mma_tf32(float* d, const uint32_t* a,
                                         const uint32_t* b) {
  asm volatile(
      "mma.sync.aligned.m16n8k8.row.col.f32.tf32.tf32.f32 "
      "{%0,%1,%2,%3}, {%4,%5,%6,%7}, {%8,%9}, {%0,%1,%2,%3};"
      : "+f"(d[0]), "+f"(d[1]), "+f"(d[2]), "+f"(d[3])
      : "r"(a[0]), "r"(a[1]), "r"(a[2]), "r"(a[3]), "r"(b[0]), "r"(b[1]));
}

// ---------------------------------------------------------------------------
// W transpose + tf32 rounding; rounds a0 into g_atf[0]; zeroes barrier flags.
// ---------------------------------------------------------------------------
__global__ __launch_bounds__(256) void transpose_kernel(const float* __restrict__ W,
                                                        const float* __restrict__ a0) {
  __shared__ float tile[32][33];
  const int n0 = blockIdx.x * 32, k0 = blockIdx.y * 32;
  const int tx = threadIdx.x, ty = threadIdx.y;  // 32 x 8
#pragma unroll
  for (int i = 0; i < 32; i += 8)
    tile[ty + i][tx] = W[(size_t)(k0 + ty + i) * G4 + n0 + tx];
  __syncthreads();
#pragma unroll
  for (int i = 0; i < 32; i += 8)
    g_Wt[(size_t)(n0 + ty + i) * INDIM + k0 + tx] = f2tf32f(tile[tx][ty + i]);
  if (blockIdx.y == 0) {  // 64 blocks x 256 thr: round a0 (32768 elems)
    const int fl = blockIdx.x * 256 + ty * 32 + tx;
    g_atf[0][fl] = f2tf32f(a0[fl]);
    g_atf[0][fl + 16384] = f2tf32f(a0[fl + 16384]);
  }
  if (blockIdx.x == 0 && blockIdx.y == 0) {  // zero all flags (4096 u32)
    const int lt = ty * 32 + tx;
#pragma unroll
    for (int j = 0; j < NGROUPS * GCTAS * 32 / 256; ++j)
      ((unsigned*)g_flags)[lt + j * 256] = 0u;
  }
}

// ---------------------------------------------------------------------------
// TF32 tensor-core GEMM (unchanged, known-good): g_xw = x@W + bias
// ---------------------------------------------------------------------------
#define BM 128
#define BN 128
#define BK 32
#define SSTR 36

__global__ __launch_bounds__(256) void xw_tc_kernel(const float* __restrict__ A,
                                                    const float* __restrict__ bias) {
  extern __shared__ float smem[];
  float* As[2] = {smem, smem + BM * SSTR};
  float* Bs[2] = {smem + 2 * BM * SSTR, smem + 3 * BM * SSTR};

  const int tid = threadIdx.x;
  const int lane = tid & 31, wid = tid >> 5;
  const int wm = (wid >> 2) * 64;
  const int wn = (wid & 3) * 32;
  const int g = lane >> 2, tg = lane & 3;
  const int n0 = blockIdx.x * BN;
  const int m0 = blockIdx.y * BM;

  const int lr = tid >> 3;
  const int lc = (tid & 7) * 4;

  float acc[4][4][4];
#pragma unroll
  for (int i = 0; i < 4; ++i)
#pragma unroll
    for (int j = 0; j < 4; ++j)
#pragma unroll
      for (int q = 0; q < 4; ++q) acc[i][j][q] = 0.0f;

  float4 pa[4], pb[4];
#pragma unroll
  for (int j = 0; j < 4; ++j) {
    const int r = lr + j * 32;
    pa[j] = *(const float4*)(A + (size_t)(m0 + r) * INDIM + lc);
    pb[j] = *(const float4*)(g_Wt + (size_t)(n0 + r) * INDIM + lc);
  }

  const int NKT = INDIM / BK;  // 16
  for (int kt = 0; kt < NKT; ++kt) {
    const int s = kt & 1;
#pragma unroll
    for (int j = 0; j < 4; ++j) {
      const int r = lr + j * 32;
      float* ap = As[s] + r * SSTR + lc;
      ap[0] = f2tf32f(pa[j].x);
      ap[1] = f2tf32f(pa[j].y);
      ap[2] = f2tf32f(pa[j].z);
      ap[3] = f2tf32f(pa[j].w);
      *(float4*)(Bs[s] + r * SSTR + lc) = pb[j];
    }
    __syncthreads();

    if (kt + 1 < NKT) {
      const int ko = (kt + 1) * BK;
#pragma unroll
      for (int j = 0; j < 4; ++j) {
        const int r = lr + j * 32;
        pa[j] = *(const float4*)(A + (size_t)(m0 + r) * INDIM + ko + lc);
        pb[j] = *(const float4*)(g_Wt + (size_t)(n0 + r) * INDIM + ko + lc);
      }
    }

#pragma unroll
    for (int k8 = 0; k8 < 4; ++k8) {
      const int kb = k8 * 8;
      uint32_t afr[4][4], bfr[4][2];
#pragma unroll
      for (int mf = 0; mf < 4; ++mf) {
        const float* ap = As[s] + (wm + mf * 16) * SSTR + kb;
        afr[mf][0] = __float_as_uint(ap[g * SSTR + tg]);
        afr[mf][1] = __float_as_uint(ap[(g + 8) * SSTR + tg]);
        afr[mf][2] = __float_as_uint(ap[g * SSTR + tg + 4]);
        afr[mf][3] = __float_as_uint(ap[(g + 8) * SSTR + tg + 4]);
      }
#pragma unroll
      for (int nf = 0; nf < 4; ++nf) {
        const float* bp = Bs[s] + (wn + nf * 8) * SSTR + kb;
        bfr[nf][0] = __float_as_uint(bp[g * SSTR + tg]);
        bfr[nf][1] = __float_as_uint(bp[g * SSTR + tg + 4]);
      }
#pragma unroll
      for (int mf = 0; mf < 4; ++mf)
#pragma unroll
        for (int nf = 0; nf < 4; ++nf)
          mma_tf32(acc[mf][nf], afr[mf], bfr[nf]);
    }
    __syncthreads();
  }

  float2 bv[4];
#pragma unroll
  for (int nf = 0; nf < 4; ++nf)
    bv[nf] = *(const float2*)(bias + n0 + wn + nf * 8 + tg * 2);
#pragma unroll
  for (int mf = 0; mf < 4; ++mf) {
    const int row0 = m0 + wm + mf * 16 + g;
#pragma unroll
    for (int nf = 0; nf < 4; ++nf) {
      const int col = n0 + wn + nf * 8 + tg * 2;
      float2 v0 = make_float2(acc[mf][nf][0] + bv[nf].x, acc[mf][nf][1] + bv[nf].y);
      float2 v1 = make_float2(acc[mf][nf][2] + bv[nf].x, acc[mf][nf][3] + bv[nf].y);
      *(float2*)(g_xw + (size_t)row0 * G4 + col) = v0;
      *(float2*)(g_xw + (size_t)(row0 + 8) * G4 + col) = v1;
    }
  }
}

// ---------------------------------------------------------------------------
// Persistent TC recurrence, batch-split into 4 groups of 16 rows x 32 CTAs.
// This round: ldmatrix fragment loads, MUFU tanh/sigmoid, all-warp polling.
// ---------------------------------------------------------------------------
#define GBATCH   16
#define RTHREADS 256
#define ASTR 516   // smem row stride (floats)
#define GSTR 68    // gate tile row stride (64 + 4 pad)

__device__ __forceinline__ float sigmoidf_(float x) {
  return __fdividef(1.0f, 1.0f + __expf(-x));
}
__device__ __forceinline__ float ftanh_(float x) {
  const float e = __expf(-2.0f * fabsf(x));
  const float r = __fdividef(1.0f - e, 1.0f + e);
  return copysignf(r, x);
}

__global__ __launch_bounds__(RTHREADS) void recur_tc_kernel(
    const float* __restrict__ U, float* __restrict__ out) {
  extern __shared__ float sm[];
  float* As = sm;                              // 16 x ASTR
  float* Us = sm + GBATCH * ASTR;              // 64 x ASTR
  float* Gs = sm + GBATCH * ASTR + 64 * ASTR;  // 2 x 16 x GSTR

  const int tid = threadIdx.x;
  const int lane = tid & 31, wid = tid >> 5;
  const int g = lane >> 2, tg = lane & 3;
  const int kw = wid >> 2;                 // K-half (0,1)
  const int nq = wid & 3;                  // n-quarter (0..3)
  const int kb0 = kw * 256;
  const int group = blockIdx.x >> 5;       // 0..3 (batch group)
  const int cg = blockIdx.x & 31;          // CTA in group
  const int hb = cg * 16;                  // h-col base (16 h per CTA)
  const int b0 = group * GBATCH;           // global batch base
  unsigned* myflag = &g_flags[group][cg * 32];
  unsigned* pollp = &g_flags[group][lane * 32];

  // --- preload U slice (tf32): Us[i*4+gate][k] = U[k][gate*512+hb+i], i<16
  for (int idx = tid; idx < 512 * 4 * 4; idx += RTHREADS) {
    const int k = idx >> 4, gate = (idx >> 2) & 3, iq = idx & 3;
    float4 v = *(const float4*)(U + (size_t)k * G4 + gate * HID + hb + iq * 4);
    Us[((iq * 4 + 0) * 4 + gate) * ASTR + k] = f2tf32f(v.x);
    Us[((iq * 4 + 1) * 4 + gate) * ASTR + k] = f2tf32f(v.y);
    Us[((iq * 4 + 2) * 4 + gate) * ASTR + k] = f2tf32f(v.z);
    Us[((iq * 4 + 3) * 4 + gate) * ASTR + k] = f2tf32f(v.w);
  }

  // ldmatrix per-lane base offsets (bytes)
  const int quad = lane >> 3, r8 = lane & 7;
  const uint32_t As_u = smem_u32(As);
  const uint32_t Us_u = smem_u32(Us);
  // A: m0:(rows 0-7,kb) m1:(rows 8-15,kb) m2:(rows 0-7,kb+4) m3:(rows 8-15,kb+4)
  const uint32_t a_base =
      As_u + ((((quad & 1) * 8 + r8) * ASTR + (quad >> 1) * 4 + kb0) * 4);
  // B: m0:(n 0-7,kb) m1:(n 0-7,kb+4) m2:(n 8-15,kb) m3:(n 8-15,kb+4)
  const uint32_t b_base =
      Us_u + (((nq * 16 + (quad >> 1) * 8 + r8) * ASTR + (quad & 1) * 4 + kb0) * 4);

  // acc columns in xw space: n_local = nq*16 + nf*8 + 2tg (+1)
  int colA[2], colB[2];
#pragma unroll
  for (int nf = 0; nf < 2; ++nf) {
    const int nlA = nq * 16 + nf * 8 + 2 * tg, nlB = nlA + 1;
    colA[nf] = (nlA & 3) * HID + hb + (nlA >> 2);
    colB[nf] = (nlB & 3) * HID + hb + (nlB >> 2);
  }
  const int bl = tid >> 4;                 // gate-phase local batch (0..15)
  const int hi = tid & 15;                 // gate-phase h index (0..15)

  // --- prefetch xw for t=0 (K-half-0 warps hold the init)
  float pxw[8];
  if (kw == 0) {
    const float* xwp = g_xw + (size_t)(b0 + g) * G4;
#pragma unroll
    for (int nf = 0; nf < 2; ++nf) {
      pxw[nf * 4 + 0] = __ldg(xwp + colA[nf]);
      pxw[nf * 4 + 1] = __ldg(xwp + colB[nf]);
      pxw[nf * 4 + 2] = __ldg(xwp + 8 * G4 + colA[nf]);
      pxw[nf * 4 + 3] = __ldg(xwp + 8 * G4 + colB[nf]);
    }
  }

  for (int t = 0; t < T_STEPS; ++t) {
    // --- acc init
    float acc[2][4];
#pragma unroll
    for (int nf = 0; nf < 2; ++nf)
#pragma unroll
      for (int q = 0; q < 4; ++q)
        acc[nf][q] = (kw == 0) ? pxw[nf * 4 + q] : 0.0f;

    // --- stage this group's a_{t-1} rows (16 x 512, tf32-rounded already)
    const float* src = g_atf[t & 1] + (size_t)b0 * HID;
#pragma unroll
    for (int j = 0; j < 8; ++j) {
      const int idx = tid + j * RTHREADS;  // 0..2047
      const int b = idx >> 7, k4 = idx & 127;
      float4 v = __ldcg((const float4*)(src + b * HID + k4 * 4));
      *(float4*)(As + b * ASTR + k4 * 4) = v;
    }
    __syncthreads();

    // --- prefetch next step's xw while mma runs
    if (kw == 0 && t + 1 < T_STEPS) {
      const float* xwp = g_xw + (size_t)(t + 1) * BATCH * G4 + (size_t)(b0 + g) * G4;
#pragma unroll
      for (int nf = 0; nf < 2; ++nf) {
        pxw[nf * 4 + 0] = __ldg(xwp + colA[nf]);
        pxw[nf * 4 + 1] = __ldg(xwp + colB[nf]);
        pxw[nf * 4 + 2] = __ldg(xwp + 8 * G4 + colA[nf]);
        pxw[nf * 4 + 3] = __ldg(xwp + 8 * G4 + colB[nf]);
      }
    }

    // --- mma: m16 x n16 over this warp's K-half, ldmatrix fragment loads
#pragma unroll 8
    for (int k8 = 0; k8 < 32; ++k8) {
      uint32_t afr[4], bb[4];
      ldsm_x4(afr, a_base + k8 * 32);
      ldsm_x4(bb, b_base + k8 * 32);
      mma_tf32(acc[0], afr, bb);
      mma_tf32(acc[1], afr, bb + 2);
    }

    // --- scatter partial preactivations (per K-half region)
    float* Gsw = Gs + kw * GBATCH * GSTR;
#pragma unroll
    for (int nf = 0; nf < 2; ++nf) {
      const int nb = nq * 16 + nf * 8 + 2 * tg;
      *(float2*)(Gsw + g * GSTR + nb) = make_float2(acc[nf][0], acc[nf][1]);
      *(float2*)(Gsw + (g + 8) * GSTR + nb) = make_float2(acc[nf][2], acc[nf][3]);
    }
    __syncthreads();

    // --- gate math: 1 output/thread (b=bl, h=hb+hi); sum the two K-halves
    {
      float4 gA = *(const float4*)(Gs + bl * GSTR + hi * 4);
      float4 gB = *(const float4*)(Gs + GBATCH * GSTR + bl * GSTR + hi * 4);
      const float gu = sigmoidf_(gA.x + gB.x);
      const float gf = sigmoidf_(gA.y + gB.y);
      const float go = sigmoidf_(gA.z + gB.z);
      const float cd = ftanh_(gA.w + gB.w);
      const float ap = As[bl * ASTR + hb + hi];  // tf32-rounded a_{t-1}
      const float ct = gu * cd + gf * ap;
      const float at = go * ftanh_(ct);
      g_atf[(t + 1) & 1][(b0 + bl) * HID + hb + hi] = f2tf32f(at);
      out[(size_t)t * BATCH * HID + (size_t)(b0 + bl) * HID + hb + hi] = at;
    }

    // --- per-group barrier: release flag, then EVERY warp acquire-polls
    if (t + 1 < T_STEPS) {
      __syncthreads();  // all threads' writes ordered before tid0's release
      if (tid == 0) {
        unsigned v = (unsigned)(t + 1);
        asm volatile("st.release.gpu.global.u32 [%0], %1;"
                     :: "l"(myflag), "r"(v) : "memory");
      }
      {
        const unsigned tgt = (unsigned)(t + 1);
        unsigned v;
        do {
          asm volatile("ld.acquire.gpu.global.u32 %0, [%1];"
                       : "=r"(v) : "l"(pollp) : "memory");
        } while (!__all_sync(0xFFFFFFFFu, v >= tgt));
      }
      // no trailing syncthreads: each warp holds its own acquire; the
      // staging-phase syncthreads re-converges the CTA before mma.
    }
  }
}

// ---------------------------------------------------------------------------
extern "C" void kernel_launch(void* const* d_in, const int* in_sizes, int n_in,
                              void* d_out, int out_size) {
  (void)in_sizes; (void)n_in; (void)out_size;
  const float* x    = (const float*)d_in[0];  // [T, B, I]
  const float* a0   = (const float*)d_in[1];  // [B, H]
  const float* W    = (const float*)d_in[2];  // [I, 4H]
  const float* U    = (const float*)d_in[3];  // [H, 4H]
  const float* bias = (const float*)d_in[4];  // [4H]
  float* out = (float*)d_out;                 // [T, B, H]

  const int smemG = 4 * BM * SSTR * sizeof(float);  // 73728 B
  cudaFuncSetAttribute(xw_tc_kernel, cudaFuncAttributeMaxDynamicSharedMemorySize,
                       smemG);
  const int smemR =
      (GBATCH * ASTR + 64 * ASTR + 2 * GBATCH * GSTR) * sizeof(float);  // 173824
  cudaFuncSetAttribute(recur_tc_kernel, cudaFuncAttributeMaxDynamicSharedMemorySize,
                       smemR);

  transpose_kernel<<<dim3(G4 / 32, INDIM / 32), dim3(32, 8)>>>(W, a0);
  xw_tc_kernel<<<dim3(G4 / BN, (T_STEPS * BATCH) / BM), 256, smemG>>>(x, bias);
  recur_tc_kernel<<<NGROUPS * GCTAS, RTHREADS, smemR>>>(U, out);
}